// round 8
// baseline (speedup 1.0000x reference)
#include <cuda_runtime.h>
#include <cuda_fp16.h>
#include <math.h>
#include <stdint.h>

#define BB 4
#define SS 2048
#define DD 1024
#define MT (BB*SS)   // 8192

// ---------------------------------------------------------------------------
// Scratch (device globals). A-side operands: hi plane only. B-side: hi+lo.
// ---------------------------------------------------------------------------
__device__ __align__(16) __half g_xh [(size_t)MT*DD];                 // A of QKV
__device__ __align__(16) __half g_Wth[(size_t)3*DD*DD], g_Wtl[(size_t)3*DD*DD];
__device__ __align__(16) __half g_Qh [(size_t)MT*DD];                 // A of scores
__device__ __align__(16) __half g_Kh [(size_t)MT*DD], g_Kl[(size_t)MT*DD];
__device__ __align__(16) __half g_Vth[(size_t)BB*DD*SS], g_Vtl[(size_t)BB*DD*SS];
__device__ __align__(16) float  g_P  [(size_t)BB*SS*SS];
__device__ __align__(16) __half g_Ph [(size_t)BB*SS*SS];              // A of PV

// ---------------------------------------------------------------------------
// Helpers
// ---------------------------------------------------------------------------
__device__ __forceinline__ uint32_t smem_u32(const void* p) {
    uint32_t a;
    asm("{ .reg .u64 t; cvta.to.shared.u64 t, %1; cvt.u32.u64 %0, t; }"
        : "=r"(a) : "l"(p));
    return a;
}

#define SWZ(o) ((uint32_t)(o) ^ ((((uint32_t)(o)) >> 3) & 0x70))

#define CP_ASYNC(dst, src) \
    asm volatile("cp.async.cg.shared.global [%0], [%1], 16;" \
                 :: "r"(dst), "l"(__cvta_generic_to_global(src)))
#define CP_COMMIT() asm volatile("cp.async.commit_group;")
#define CP_WAIT0()  asm volatile("cp.async.wait_group 0;")

#define LDM_X4(r, addr) \
    asm volatile("ldmatrix.sync.aligned.m8n8.x4.shared.b16 {%0,%1,%2,%3}, [%4];" \
        : "=r"((r)[0]), "=r"((r)[1]), "=r"((r)[2]), "=r"((r)[3]) : "r"(addr))

// f32-accum HMMA (hi terms)
#define MMA_F32(d, a, b0v, b1v) \
    asm volatile("mma.sync.aligned.m16n8k16.row.col.f32.f16.f16.f32 " \
        "{%0,%1,%2,%3}, {%4,%5,%6,%7}, {%8,%9}, {%0,%1,%2,%3};" \
        : "+f"((d)[0]), "+f"((d)[1]), "+f"((d)[2]), "+f"((d)[3]) \
        : "r"((a)[0]), "r"((a)[1]), "r"((a)[2]), "r"((a)[3]), "r"(b0v), "r"(b1v))

// f16-accum HMMA (lo correction terms; values tiny, range safe)
#define MMA_F16H(d, a, b0v, b1v) \
    asm volatile("mma.sync.aligned.m16n8k16.row.col.f16.f16.f16.f16 " \
        "{%0,%1}, {%2,%3,%4,%5}, {%6,%7}, {%0,%1};" \
        : "+r"((d)[0]), "+r"((d)[1]) \
        : "r"((a)[0]), "r"((a)[1]), "r"((a)[2]), "r"((a)[3]), "r"(b0v), "r"(b1v))

__device__ __forceinline__ uint32_t packh2(float a, float b) {
    __half2 h = __floats2half2_rn(a, b);
    return *(uint32_t*)&h;
}
__device__ __forceinline__ void split2(float a, float b, uint32_t& hi, uint32_t& lo) {
    __half ha = __float2half_rn(a), hb = __float2half_rn(b);
    __half la = __float2half_rn(a - __half2float(ha));
    __half lb = __float2half_rn(b - __half2float(hb));
    hi = (uint32_t)*(uint16_t*)&ha | ((uint32_t)*(uint16_t*)&hb << 16);
    lo = (uint32_t)*(uint16_t*)&la | ((uint32_t)*(uint16_t*)&lb << 16);
}

// ---------------------------------------------------------------------------
// SMEM: stage = A(16KB) + BH(16KB) + BL(16KB) = 48KB; 2 stages = 96KB
// Epilogue (z==2) reuses the same smem for the transpose staging.
// ---------------------------------------------------------------------------
#define OFF_A  0
#define OFF_BH 16384
#define OFF_BL 32768
#define STG    49152
#define SM_TOT (2*STG)   // 98304

// transpose-staging planes (epilogue reuse): 128 rows x 130 half = 260B rows
#define TRROW 260
#define TRH   0
#define TRL   33280   // 128*260

// ---------------------------------------------------------------------------
// Load one BK=64 chunk (3 planes) via cp.async. 12 x 16B per thread.
// ---------------------------------------------------------------------------
__device__ __forceinline__ void load_chunk(
    uint32_t stg,
    const __half* __restrict__ A, int lda,
    const __half* __restrict__ Bh, const __half* __restrict__ Bl, int ldb,
    int k0, int tid)
{
#pragma unroll
    for (int i = 0; i < 4; ++i) {
        int u = tid + i * 256, row = u >> 3, ch = u & 7;
        uint32_t off = SWZ(row * 128 + ch * 16);
        size_t ga = (size_t)row * lda + k0 + ch * 8;
        size_t gb = (size_t)row * ldb + k0 + ch * 8;
        CP_ASYNC(stg + OFF_A  + off, A  + ga);
        CP_ASYNC(stg + OFF_BH + off, Bh + gb);
        CP_ASYNC(stg + OFF_BL + off, Bl + gb);
    }
}

// ---------------------------------------------------------------------------
// Compute one BK=64 chunk. Two sub-passes to bound register liveness:
//   pass 1: acc(f32) += A*Bh   (f32-accum HMMA)
//   pass 2: accL(f16) += A*Bl  (f16-accum HMMA), folded into acc at chunk end
// ---------------------------------------------------------------------------
__device__ __forceinline__ void compute_chunk(
    uint32_t stg, int wm, int wn, int lane, float (&acc)[4][4][4])
{
    const int rsel = lane & 15;
    const int csel = lane >> 4;

    // pass 1: hi terms
#pragma unroll
    for (int ks = 0; ks < 4; ++ks) {
        const uint32_t cb = (ks * 2 + csel) * 16;
        uint32_t bh[2][4];
#pragma unroll
        for (int j2 = 0; j2 < 2; ++j2)
            LDM_X4(bh[j2], stg + OFF_BH + SWZ((wn * 32 + j2 * 16 + rsel) * 128 + cb));
#pragma unroll
        for (int i = 0; i < 4; ++i) {
            uint32_t ah[4];
            LDM_X4(ah, stg + OFF_A + SWZ((wm * 64 + i * 16 + rsel) * 128 + cb));
#pragma unroll
            for (int j = 0; j < 4; ++j)
                MMA_F32(acc[i][j], ah, bh[j >> 1][j & 1], bh[j >> 1][(j & 1) + 2]);
        }
    }

    // pass 2: lo terms in f16 accum
    uint32_t accL[4][4][2];
#pragma unroll
    for (int i = 0; i < 4; ++i)
#pragma unroll
        for (int j = 0; j < 4; ++j) { accL[i][j][0] = 0u; accL[i][j][1] = 0u; }

#pragma unroll
    for (int ks = 0; ks < 4; ++ks) {
        const uint32_t cb = (ks * 2 + csel) * 16;
        uint32_t bl[2][4];
#pragma unroll
        for (int j2 = 0; j2 < 2; ++j2)
            LDM_X4(bl[j2], stg + OFF_BL + SWZ((wn * 32 + j2 * 16 + rsel) * 128 + cb));
#pragma unroll
        for (int i = 0; i < 4; ++i) {
            uint32_t ah[4];
            LDM_X4(ah, stg + OFF_A + SWZ((wm * 64 + i * 16 + rsel) * 128 + cb));
#pragma unroll
            for (int j = 0; j < 4; ++j)
                MMA_F16H(accL[i][j], ah, bl[j >> 1][j & 1], bl[j >> 1][(j & 1) + 2]);
        }
    }

    // fold lo into fp32 acc
#pragma unroll
    for (int i = 0; i < 4; ++i) {
#pragma unroll
        for (int j = 0; j < 4; ++j) {
            float2 f0 = __half22float2(*(__half2*)&accL[i][j][0]);
            float2 f1 = __half22float2(*(__half2*)&accL[i][j][1]);
            acc[i][j][0] += f0.x; acc[i][j][1] += f0.y;
            acc[i][j][2] += f1.x; acc[i][j][3] += f1.y;
        }
    }
}

// ---------------------------------------------------------------------------
// GEMM mainloop: single __syncthreads per chunk.
// ---------------------------------------------------------------------------
__device__ __forceinline__ void gemm_f16(
    const __half* __restrict__ A, int lda,
    const __half* __restrict__ Bh, const __half* __restrict__ Bl, int ldb,
    int nCh, float (&acc)[4][4][4], uint32_t sb, int tid)
{
    const int lane = tid & 31, w = tid >> 5;
    const int wm = w & 1, wn = w >> 1;

#pragma unroll
    for (int i = 0; i < 4; ++i)
#pragma unroll
        for (int j = 0; j < 4; ++j)
#pragma unroll
            for (int q = 0; q < 4; ++q) acc[i][j][q] = 0.f;

    load_chunk(sb, A, lda, Bh, Bl, ldb, 0, tid);
    CP_COMMIT();

    for (int c = 0; c < nCh; ++c) {
        CP_WAIT0();
        __syncthreads();
        if (c + 1 < nCh) {
            load_chunk(sb + ((c + 1) & 1) * STG, A, lda, Bh, Bl, ldb,
                       (c + 1) * 64, tid);
            CP_COMMIT();
        }
        compute_chunk(sb + (c & 1) * STG, wm, wn, lane, acc);
    }
}

// ---------------------------------------------------------------------------
// 1) QKV GEMM: z=0->Q (fp16 hi), z=1->K (fp16 split),
//    z=2->V transposed fp16 split (fused transpose via smem). grid (8, 64, 3)
// ---------------------------------------------------------------------------
__global__ void __launch_bounds__(256, 2) qkv_gemm()
{
    extern __shared__ char smem[];
    const uint32_t sb = smem_u32(smem);
    const int tid = threadIdx.x, lane = tid & 31, w = tid >> 5;
    const int z = blockIdx.z;
    const int n0 = blockIdx.x * 128;
    const int m0 = blockIdx.y * 128;

    float acc[4][4][4];
    gemm_f16(g_xh + (size_t)m0 * DD, DD,
             g_Wth + (size_t)z * DD * DD + (size_t)n0 * DD,
             g_Wtl + (size_t)z * DD * DD + (size_t)n0 * DD, DD,
             16, acc, sb, tid);

    const int tg = lane >> 2, t4 = lane & 3;
    const int wm = w & 1, wn = w >> 1;

    if (z == 2) {
        // Fused V transpose: stage hi/lo fp16 tile in smem, write transposed.
        __syncthreads();  // mainloop smem dead everywhere before reuse
#pragma unroll
        for (int i = 0; i < 4; ++i) {
#pragma unroll
            for (int j = 0; j < 4; ++j) {
                const int rl = wm * 64 + i * 16 + tg;
                const int cl = wn * 32 + j * 8 + t4 * 2;
                uint32_t hi, lo;
                split2(acc[i][j][0], acc[i][j][1], hi, lo);
                *(uint32_t*)(smem + TRH + rl * TRROW + cl * 2) = hi;
                *(uint32_t*)(smem + TRL + rl * TRROW + cl * 2) = lo;
                split2(acc[i][j][2], acc[i][j][3], hi, lo);
                *(uint32_t*)(smem + TRH + (rl + 8) * TRROW + cl * 2) = hi;
                *(uint32_t*)(smem + TRL + (rl + 8) * TRROW + cl * 2) = lo;
            }
        }
        __syncthreads();
        const int b = m0 >> 11, s0r = m0 & 2047;
        const int d = tid >> 1, sh = tid & 1;
        __half* dstH = g_Vth + ((size_t)b * DD + n0 + d) * SS + s0r + sh * 64;
        __half* dstL = g_Vtl + ((size_t)b * DD + n0 + d) * SS + s0r + sh * 64;
#pragma unroll
        for (int g = 0; g < 8; ++g) {
            uint32_t wh[4], wl[4];
#pragma unroll
            for (int e = 0; e < 4; ++e) {
                const int s = sh * 64 + g * 8 + e * 2;
                uint32_t h0 = *(uint16_t*)(smem + TRH + s * TRROW + d * 2);
                uint32_t h1 = *(uint16_t*)(smem + TRH + (s + 1) * TRROW + d * 2);
                wh[e] = h0 | (h1 << 16);
                uint32_t l0 = *(uint16_t*)(smem + TRL + s * TRROW + d * 2);
                uint32_t l1 = *(uint16_t*)(smem + TRL + (s + 1) * TRROW + d * 2);
                wl[e] = l0 | (l1 << 16);
            }
            *(uint4*)(dstH + g * 8) = make_uint4(wh[0], wh[1], wh[2], wh[3]);
            *(uint4*)(dstL + g * 8) = make_uint4(wl[0], wl[1], wl[2], wl[3]);
        }
        return;
    }

#pragma unroll
    for (int i = 0; i < 4; ++i) {
#pragma unroll
        for (int j = 0; j < 4; ++j) {
            const int r = m0 + wm * 64 + i * 16 + tg;
            const int c = n0 + wn * 32 + j * 8 + t4 * 2;
            if (z == 0) {
                *(uint32_t*)(g_Qh + (size_t)r * DD + c) =
                    packh2(acc[i][j][0], acc[i][j][1]);
                *(uint32_t*)(g_Qh + (size_t)(r + 8) * DD + c) =
                    packh2(acc[i][j][2], acc[i][j][3]);
            } else {
                uint32_t hi, lo;
                split2(acc[i][j][0], acc[i][j][1], hi, lo);
                *(uint32_t*)(g_Kh + (size_t)r * DD + c) = hi;
                *(uint32_t*)(g_Kl + (size_t)r * DD + c) = lo;
                split2(acc[i][j][2], acc[i][j][3], hi, lo);
                *(uint32_t*)(g_Kh + (size_t)(r + 8) * DD + c) = hi;
                *(uint32_t*)(g_Kl + (size_t)(r + 8) * DD + c) = lo;
            }
        }
    }
}

// ---------------------------------------------------------------------------
// 2) Scores: P = scale * Q @ K^T, causal tiles only. grid (136, 4)
// ---------------------------------------------------------------------------
__global__ void __launch_bounds__(256, 2) scores_gemm()
{
    const int t = blockIdx.x, b = blockIdx.y;
    int it = (int)floorf((sqrtf(8.f * (float)t + 1.f) - 1.f) * 0.5f);
    while ((it + 1) * (it + 2) / 2 <= t) ++it;
    while (it * (it + 1) / 2 > t) --it;
    const int jt = t - it * (it + 1) / 2;

    extern __shared__ char smem[];
    const uint32_t sb = smem_u32(smem);
    const int tid = threadIdx.x, lane = tid & 31, w = tid >> 5;

    float acc[4][4][4];
    gemm_f16(g_Qh + ((size_t)b * SS + it * 128) * DD, DD,
             g_Kh + ((size_t)b * SS + jt * 128) * DD,
             g_Kl + ((size_t)b * SS + jt * 128) * DD, DD,
             16, acc, sb, tid);

    const int tg = lane >> 2, t4 = lane & 3;
    const int wm = w & 1, wn = w >> 1;
    const float scale = 0.03125f;  // 1/sqrt(1024)
#pragma unroll
    for (int i = 0; i < 4; ++i) {
#pragma unroll
        for (int j = 0; j < 4; ++j) {
            const int r = it * 128 + wm * 64 + i * 16 + tg;
            const int c = jt * 128 + wn * 32 + j * 8 + t4 * 2;
            float* base = g_P + (size_t)b * SS * SS;
            *(float2*)(base + (size_t)r * SS + c) =
                make_float2(acc[i][j][0] * scale, acc[i][j][1] * scale);
            *(float2*)(base + (size_t)(r + 8) * SS + c) =
                make_float2(acc[i][j][2] * scale, acc[i][j][3] * scale);
        }
    }
}

// ---------------------------------------------------------------------------
// 3) PV: O = P @ V. Heavy row-blocks first. grid (8, 16, 4)
// ---------------------------------------------------------------------------
__global__ void __launch_bounds__(256, 2) pv_gemm(float* __restrict__ out)
{
    extern __shared__ char smem[];
    const uint32_t sb = smem_u32(smem);
    const int tid = threadIdx.x, lane = tid & 31, w = tid >> 5;
    const int n0 = blockIdx.x * 128;
    const int it = 15 - blockIdx.y;   // heavy-first
    const int b = blockIdx.z;

    float acc[4][4][4];
    gemm_f16(g_Ph + ((size_t)b * SS + it * 128) * SS, SS,
             g_Vth + ((size_t)b * DD + n0) * SS,
             g_Vtl + ((size_t)b * DD + n0) * SS, SS,
             (it + 1) * 2, acc, sb, tid);

    const int tg = lane >> 2, t4 = lane & 3;
    const int wm = w & 1, wn = w >> 1;
#pragma unroll
    for (int i = 0; i < 4; ++i) {
#pragma unroll
        for (int j = 0; j < 4; ++j) {
            const size_t r = (size_t)b * SS + it * 128 + wm * 64 + i * 16 + tg;
            const int c = n0 + wn * 32 + j * 8 + t4 * 2;
            *(float2*)(out + r * DD + c) = make_float2(acc[i][j][0], acc[i][j][1]);
            *(float2*)(out + (r + 8) * DD + c) = make_float2(acc[i][j][2], acc[i][j][3]);
        }
    }
}

// ---------------------------------------------------------------------------
// Prep: x -> fp16 hi plane. grid 8192, block 256 (4 floats/thread)
// ---------------------------------------------------------------------------
__global__ void __launch_bounds__(256) prep_x_kernel(const float* __restrict__ in)
{
    size_t i = (size_t)blockIdx.x * 256 + threadIdx.x;
    float4 v = ((const float4*)in)[i];
    uint2 H;
    H.x = packh2(v.x, v.y);
    H.y = packh2(v.z, v.w);
    ((uint2*)g_xh)[i] = H;
}

// ---------------------------------------------------------------------------
// Prep: transpose + fp16 split W. grid (32, 32, 3), block (32, 8)
// ---------------------------------------------------------------------------
__global__ void __launch_bounds__(256) prep_w_kernel(
    const float* __restrict__ WQ, const float* __restrict__ WK,
    const float* __restrict__ WV)
{
    __shared__ float t[32][33];
    const float* W = (blockIdx.z == 0) ? WQ : (blockIdx.z == 1) ? WK : WV;
    const int n0 = blockIdx.x * 32, k0 = blockIdx.y * 32;
    const int tx = threadIdx.x, ty = threadIdx.y;
#pragma unroll
    for (int j = 0; j < 32; j += 8)
        t[ty + j][tx] = W[(size_t)(k0 + ty + j) * DD + n0 + tx];
    __syncthreads();
    __half* oh = g_Wth + (size_t)blockIdx.z * DD * DD;
    __half* ol = g_Wtl + (size_t)blockIdx.z * DD * DD;
#pragma unroll
    for (int j = 0; j < 32; j += 8) {
        float v = t[tx][ty + j];
        __half h = __float2half_rn(v);
        __half l = __float2half_rn(v - __half2float(h));
        size_t o = (size_t)(n0 + ty + j) * DD + k0 + tx;
        oh[o] = h;
        ol[o] = l;
    }
}

// ---------------------------------------------------------------------------
// Softmax: fp32 P row -> fp16 hi plane, zero-padded to 128-tile edge.
// grid 8192, block 256
// ---------------------------------------------------------------------------
__global__ void __launch_bounds__(256) softmax_kernel()
{
    const int row = blockIdx.x;
    const int b = row >> 11;
    const int i = row & 2047;
    const float* p = g_P + ((size_t)b * SS + i) * SS;
    __half* ph = g_Ph + ((size_t)b * SS + i) * SS;
    const int L = i + 1;
    const int E = ((i >> 7) + 1) << 7;
    const int tid = threadIdx.x;
    const int base = tid * 8;

    __shared__ float red[256];

    float vals[8];
    {
        float4 v0 = ((const float4*)p)[tid * 2];
        float4 v1 = ((const float4*)p)[tid * 2 + 1];
        vals[0] = v0.x; vals[1] = v0.y; vals[2] = v0.z; vals[3] = v0.w;
        vals[4] = v1.x; vals[5] = v1.y; vals[6] = v1.z; vals[7] = v1.w;
    }
    float m = -INFINITY;
#pragma unroll
    for (int u = 0; u < 8; u++) {
        if (base + u >= L) vals[u] = -INFINITY;
        m = fmaxf(m, vals[u]);
    }
    red[tid] = m;
    __syncthreads();
    for (int s = 128; s > 0; s >>= 1) {
        if (tid < s) red[tid] = fmaxf(red[tid], red[tid + s]);
        __syncthreads();
    }
    m = red[0];
    __syncthreads();

    float sum = 0.f;
#pragma unroll
    for (int u = 0; u < 8; u++) {
        vals[u] = (base + u < L) ? expf(vals[u] - m) : 0.f;
        sum += vals[u];
    }
    red[tid] = sum;
    __syncthreads();
    for (int s = 128; s > 0; s >>= 1) {
        if (tid < s) red[tid] += red[tid + s];
        __syncthreads();
    }
    const float inv = 1.f / red[0];

    if (base < E) {
        uint4 H;
        H.x = packh2(vals[0] * inv, vals[1] * inv);
        H.y = packh2(vals[2] * inv, vals[3] * inv);
        H.z = packh2(vals[4] * inv, vals[5] * inv);
        H.w = packh2(vals[6] * inv, vals[7] * inv);
        *(uint4*)(ph + base) = H;
    }
}

// ---------------------------------------------------------------------------
extern "C" void kernel_launch(void* const* d_in, const int* in_sizes, int n_in,
                              void* d_out, int out_size)
{
    (void)in_sizes; (void)n_in; (void)out_size;
    const float* x  = (const float*)d_in[0];
    const float* WQ = (const float*)d_in[1];
    const float* WK = (const float*)d_in[2];
    const float* WV = (const float*)d_in[3];
    float* out = (float*)d_out;

    cudaFuncSetAttribute(qkv_gemm,    cudaFuncAttributeMaxDynamicSharedMemorySize, SM_TOT);
    cudaFuncSetAttribute(scores_gemm, cudaFuncAttributeMaxDynamicSharedMemorySize, SM_TOT);
    cudaFuncSetAttribute(pv_gemm,     cudaFuncAttributeMaxDynamicSharedMemorySize, SM_TOT);

    prep_x_kernel<<<8192, 256>>>(x);
    prep_w_kernel<<<dim3(32, 32, 3), dim3(32, 8)>>>(WQ, WK, WV);
    qkv_gemm<<<dim3(8, 64, 3), 256, SM_TOT>>>();
    scores_gemm<<<dim3(136, 4), 256, SM_TOT>>>();
    softmax_kernel<<<8192, 256>>>();
    pv_gemm<<<dim3(8, 16, 4), 256, SM_TOT>>>(out);
}

// round 9
// speedup vs baseline: 1.1921x; 1.1921x over previous
#include <cuda_runtime.h>
#include <cuda_fp16.h>
#include <math.h>
#include <stdint.h>

#define BB 4
#define SS 2048
#define DD 1024
#define MT (BB*SS)   // 8192

// ---------------------------------------------------------------------------
// Scratch (device globals). A-side operands: hi plane only. B-side: hi+lo.
// ---------------------------------------------------------------------------
__device__ __align__(16) __half g_xh [(size_t)MT*DD];                 // A of QKV
__device__ __align__(16) __half g_Wth[(size_t)3*DD*DD], g_Wtl[(size_t)3*DD*DD];
__device__ __align__(16) __half g_Qh [(size_t)MT*DD];                 // A of scores
__device__ __align__(16) __half g_Kh [(size_t)MT*DD], g_Kl[(size_t)MT*DD];
__device__ __align__(16) __half g_Vth[(size_t)BB*DD*SS], g_Vtl[(size_t)BB*DD*SS];
__device__ __align__(16) float  g_P  [(size_t)BB*SS*SS];
__device__ __align__(16) __half g_Ph [(size_t)BB*SS*SS];              // A of PV

// ---------------------------------------------------------------------------
// Helpers
// ---------------------------------------------------------------------------
__device__ __forceinline__ uint32_t smem_u32(const void* p) {
    uint32_t a;
    asm("{ .reg .u64 t; cvta.to.shared.u64 t, %1; cvt.u32.u64 %0, t; }"
        : "=r"(a) : "l"(p));
    return a;
}

#define SWZ(o) ((uint32_t)(o) ^ ((((uint32_t)(o)) >> 3) & 0x70))

#define CP_ASYNC(dst, src) \
    asm volatile("cp.async.cg.shared.global [%0], [%1], 16;" \
                 :: "r"(dst), "l"(__cvta_generic_to_global(src)))
#define CP_COMMIT() asm volatile("cp.async.commit_group;")
#define CP_WAIT0()  asm volatile("cp.async.wait_group 0;")

#define LDM_X4(r, addr) \
    asm volatile("ldmatrix.sync.aligned.m8n8.x4.shared.b16 {%0,%1,%2,%3}, [%4];" \
        : "=r"((r)[0]), "=r"((r)[1]), "=r"((r)[2]), "=r"((r)[3]) : "r"(addr))

#define MMA_F16(d, a, b0v, b1v) \
    asm volatile("mma.sync.aligned.m16n8k16.row.col.f32.f16.f16.f32 " \
        "{%0,%1,%2,%3}, {%4,%5,%6,%7}, {%8,%9}, {%0,%1,%2,%3};" \
        : "+f"((d)[0]), "+f"((d)[1]), "+f"((d)[2]), "+f"((d)[3]) \
        : "r"((a)[0]), "r"((a)[1]), "r"((a)[2]), "r"((a)[3]), "r"(b0v), "r"(b1v))

__device__ __forceinline__ uint32_t packh2(float a, float b) {
    __half2 h = __floats2half2_rn(a, b);
    return *(uint32_t*)&h;
}
__device__ __forceinline__ void split2(float a, float b, uint32_t& hi, uint32_t& lo) {
    __half ha = __float2half_rn(a), hb = __float2half_rn(b);
    __half la = __float2half_rn(a - __half2float(ha));
    __half lb = __float2half_rn(b - __half2float(hb));
    hi = (uint32_t)*(uint16_t*)&ha | ((uint32_t)*(uint16_t*)&hb << 16);
    lo = (uint32_t)*(uint16_t*)&la | ((uint32_t)*(uint16_t*)&lb << 16);
}

// ---------------------------------------------------------------------------
// SMEM: stage = A(16KB) + BH(16KB) + BL(16KB) = 48KB; 2 stages = 96KB
// Epilogue (z==2) reuses the same smem for the transpose staging.
// ---------------------------------------------------------------------------
#define OFF_A  0
#define OFF_BH 16384
#define OFF_BL 32768
#define STG    49152
#define SM_TOT (2*STG)   // 98304

// transpose-staging planes (epilogue reuse): 128 rows x 130 half = 260B rows
#define TRROW 260
#define TRH   0
#define TRL   33280   // 128*260

// ---------------------------------------------------------------------------
// Load one BK=64 chunk (3 planes) via cp.async. 12 x 16B per thread.
// ---------------------------------------------------------------------------
__device__ __forceinline__ void load_chunk(
    uint32_t stg,
    const __half* __restrict__ A, int lda,
    const __half* __restrict__ Bh, const __half* __restrict__ Bl, int ldb,
    int k0, int tid)
{
#pragma unroll
    for (int i = 0; i < 4; ++i) {
        int u = tid + i * 256, row = u >> 3, ch = u & 7;
        uint32_t off = SWZ(row * 128 + ch * 16);
        size_t ga = (size_t)row * lda + k0 + ch * 8;
        size_t gb = (size_t)row * ldb + k0 + ch * 8;
        CP_ASYNC(stg + OFF_A  + off, A  + ga);
        CP_ASYNC(stg + OFF_BH + off, Bh + gb);
        CP_ASYNC(stg + OFF_BL + off, Bl + gb);
    }
}

// ---------------------------------------------------------------------------
// Compute one BK=64 chunk: warp tile 64x32, 2-term fp16: acc += A*(Bh+Bl)
// Single interleaved pass (proven R7 form).
// ---------------------------------------------------------------------------
__device__ __forceinline__ void compute_chunk(
    uint32_t stg, int wm, int wn, int lane, float (&acc)[4][4][4])
{
    const int rsel = lane & 15;
    const int csel = lane >> 4;
#pragma unroll
    for (int ks = 0; ks < 4; ++ks) {
        uint32_t ah[4][4], bh[2][4], bl[2][4];
#pragma unroll
        for (int i = 0; i < 4; ++i) {
            uint32_t off = SWZ((wm * 64 + i * 16 + rsel) * 128 + (ks * 2 + csel) * 16);
            LDM_X4(ah[i], stg + OFF_A + off);
        }
#pragma unroll
        for (int j2 = 0; j2 < 2; ++j2) {
            uint32_t off = SWZ((wn * 32 + j2 * 16 + rsel) * 128 + (ks * 2 + csel) * 16);
            LDM_X4(bh[j2], stg + OFF_BH + off);
            LDM_X4(bl[j2], stg + OFF_BL + off);
        }
#pragma unroll
        for (int i = 0; i < 4; ++i) {
#pragma unroll
            for (int j = 0; j < 4; ++j) {
                const int j2 = j >> 1, s = j & 1;
                MMA_F16(acc[i][j], ah[i], bh[j2][s], bh[j2][s + 2]);
                MMA_F16(acc[i][j], ah[i], bl[j2][s], bl[j2][s + 2]);
            }
        }
    }
}

// ---------------------------------------------------------------------------
// GEMM mainloop: single __syncthreads per chunk.
// ---------------------------------------------------------------------------
__device__ __forceinline__ void gemm_f16(
    const __half* __restrict__ A, int lda,
    const __half* __restrict__ Bh, const __half* __restrict__ Bl, int ldb,
    int nCh, float (&acc)[4][4][4], uint32_t sb, int tid)
{
    const int lane = tid & 31, w = tid >> 5;
    const int wm = w & 1, wn = w >> 1;

#pragma unroll
    for (int i = 0; i < 4; ++i)
#pragma unroll
        for (int j = 0; j < 4; ++j)
#pragma unroll
            for (int q = 0; q < 4; ++q) acc[i][j][q] = 0.f;

    load_chunk(sb, A, lda, Bh, Bl, ldb, 0, tid);
    CP_COMMIT();

    for (int c = 0; c < nCh; ++c) {
        CP_WAIT0();
        __syncthreads();
        if (c + 1 < nCh) {
            load_chunk(sb + ((c + 1) & 1) * STG, A, lda, Bh, Bl, ldb,
                       (c + 1) * 64, tid);
            CP_COMMIT();
        }
        compute_chunk(sb + (c & 1) * STG, wm, wn, lane, acc);
    }
}

// ---------------------------------------------------------------------------
// 1) QKV GEMM: z=0->Q (fp16 hi), z=1->K (fp16 split),
//    z=2->V transposed fp16 split (fused transpose via smem). grid (8, 64, 3)
// ---------------------------------------------------------------------------
__global__ void __launch_bounds__(256, 2) qkv_gemm()
{
    extern __shared__ char smem[];
    const uint32_t sb = smem_u32(smem);
    const int tid = threadIdx.x, lane = tid & 31, w = tid >> 5;
    const int z = blockIdx.z;
    const int n0 = blockIdx.x * 128;
    const int m0 = blockIdx.y * 128;

    float acc[4][4][4];
    gemm_f16(g_xh + (size_t)m0 * DD, DD,
             g_Wth + (size_t)z * DD * DD + (size_t)n0 * DD,
             g_Wtl + (size_t)z * DD * DD + (size_t)n0 * DD, DD,
             16, acc, sb, tid);

    const int tg = lane >> 2, t4 = lane & 3;
    const int wm = w & 1, wn = w >> 1;

    if (z == 2) {
        // Fused V transpose: stage hi/lo fp16 tile in smem, write transposed.
        __syncthreads();  // mainloop smem dead everywhere before reuse
#pragma unroll
        for (int i = 0; i < 4; ++i) {
#pragma unroll
            for (int j = 0; j < 4; ++j) {
                const int rl = wm * 64 + i * 16 + tg;
                const int cl = wn * 32 + j * 8 + t4 * 2;
                uint32_t hi, lo;
                split2(acc[i][j][0], acc[i][j][1], hi, lo);
                *(uint32_t*)(smem + TRH + rl * TRROW + cl * 2) = hi;
                *(uint32_t*)(smem + TRL + rl * TRROW + cl * 2) = lo;
                split2(acc[i][j][2], acc[i][j][3], hi, lo);
                *(uint32_t*)(smem + TRH + (rl + 8) * TRROW + cl * 2) = hi;
                *(uint32_t*)(smem + TRL + (rl + 8) * TRROW + cl * 2) = lo;
            }
        }
        __syncthreads();
        const int b = m0 >> 11, s0r = m0 & 2047;
        const int d = tid >> 1, sh = tid & 1;
        __half* dstH = g_Vth + ((size_t)b * DD + n0 + d) * SS + s0r + sh * 64;
        __half* dstL = g_Vtl + ((size_t)b * DD + n0 + d) * SS + s0r + sh * 64;
#pragma unroll
        for (int g = 0; g < 8; ++g) {
            uint32_t wh[4], wl[4];
#pragma unroll
            for (int e = 0; e < 4; ++e) {
                const int s = sh * 64 + g * 8 + e * 2;
                uint32_t h0 = *(uint16_t*)(smem + TRH + s * TRROW + d * 2);
                uint32_t h1 = *(uint16_t*)(smem + TRH + (s + 1) * TRROW + d * 2);
                wh[e] = h0 | (h1 << 16);
                uint32_t l0 = *(uint16_t*)(smem + TRL + s * TRROW + d * 2);
                uint32_t l1 = *(uint16_t*)(smem + TRL + (s + 1) * TRROW + d * 2);
                wl[e] = l0 | (l1 << 16);
            }
            *(uint4*)(dstH + g * 8) = make_uint4(wh[0], wh[1], wh[2], wh[3]);
            *(uint4*)(dstL + g * 8) = make_uint4(wl[0], wl[1], wl[2], wl[3]);
        }
        return;
    }

#pragma unroll
    for (int i = 0; i < 4; ++i) {
#pragma unroll
        for (int j = 0; j < 4; ++j) {
            const int r = m0 + wm * 64 + i * 16 + tg;
            const int c = n0 + wn * 32 + j * 8 + t4 * 2;
            if (z == 0) {
                *(uint32_t*)(g_Qh + (size_t)r * DD + c) =
                    packh2(acc[i][j][0], acc[i][j][1]);
                *(uint32_t*)(g_Qh + (size_t)(r + 8) * DD + c) =
                    packh2(acc[i][j][2], acc[i][j][3]);
            } else {
                uint32_t hi, lo;
                split2(acc[i][j][0], acc[i][j][1], hi, lo);
                *(uint32_t*)(g_Kh + (size_t)r * DD + c) = hi;
                *(uint32_t*)(g_Kl + (size_t)r * DD + c) = lo;
                split2(acc[i][j][2], acc[i][j][3], hi, lo);
                *(uint32_t*)(g_Kh + (size_t)(r + 8) * DD + c) = hi;
                *(uint32_t*)(g_Kl + (size_t)(r + 8) * DD + c) = lo;
            }
        }
    }
}

// ---------------------------------------------------------------------------
// 2) Scores: P = scale * Q @ K^T, causal tiles only. grid (136, 4)
// ---------------------------------------------------------------------------
__global__ void __launch_bounds__(256, 2) scores_gemm()
{
    const int t = blockIdx.x, b = blockIdx.y;
    int it = (int)floorf((sqrtf(8.f * (float)t + 1.f) - 1.f) * 0.5f);
    while ((it + 1) * (it + 2) / 2 <= t) ++it;
    while (it * (it + 1) / 2 > t) --it;
    const int jt = t - it * (it + 1) / 2;

    extern __shared__ char smem[];
    const uint32_t sb = smem_u32(smem);
    const int tid = threadIdx.x, lane = tid & 31, w = tid >> 5;

    float acc[4][4][4];
    gemm_f16(g_Qh + ((size_t)b * SS + it * 128) * DD, DD,
             g_Kh + ((size_t)b * SS + jt * 128) * DD,
             g_Kl + ((size_t)b * SS + jt * 128) * DD, DD,
             16, acc, sb, tid);

    const int tg = lane >> 2, t4 = lane & 3;
    const int wm = w & 1, wn = w >> 1;
    const float scale = 0.03125f;  // 1/sqrt(1024)
#pragma unroll
    for (int i = 0; i < 4; ++i) {
#pragma unroll
        for (int j = 0; j < 4; ++j) {
            const int r = it * 128 + wm * 64 + i * 16 + tg;
            const int c = jt * 128 + wn * 32 + j * 8 + t4 * 2;
            float* base = g_P + (size_t)b * SS * SS;
            *(float2*)(base + (size_t)r * SS + c) =
                make_float2(acc[i][j][0] * scale, acc[i][j][1] * scale);
            *(float2*)(base + (size_t)(r + 8) * SS + c) =
                make_float2(acc[i][j][2] * scale, acc[i][j][3] * scale);
        }
    }
}

// ---------------------------------------------------------------------------
// 3) PV: O = P @ V. Heavy row-blocks first. grid (8, 16, 4)
// ---------------------------------------------------------------------------
__global__ void __launch_bounds__(256, 2) pv_gemm(float* __restrict__ out)
{
    extern __shared__ char smem[];
    const uint32_t sb = smem_u32(smem);
    const int tid = threadIdx.x, lane = tid & 31, w = tid >> 5;
    const int n0 = blockIdx.x * 128;
    const int it = 15 - blockIdx.y;   // heavy-first
    const int b = blockIdx.z;

    float acc[4][4][4];
    gemm_f16(g_Ph + ((size_t)b * SS + it * 128) * SS, SS,
             g_Vth + ((size_t)b * DD + n0) * SS,
             g_Vtl + ((size_t)b * DD + n0) * SS, SS,
             (it + 1) * 2, acc, sb, tid);

    const int tg = lane >> 2, t4 = lane & 3;
    const int wm = w & 1, wn = w >> 1;
#pragma unroll
    for (int i = 0; i < 4; ++i) {
#pragma unroll
        for (int j = 0; j < 4; ++j) {
            const size_t r = (size_t)b * SS + it * 128 + wm * 64 + i * 16 + tg;
            const int c = n0 + wn * 32 + j * 8 + t4 * 2;
            *(float2*)(out + r * DD + c) = make_float2(acc[i][j][0], acc[i][j][1]);
            *(float2*)(out + (r + 8) * DD + c) = make_float2(acc[i][j][2], acc[i][j][3]);
        }
    }
}

// ---------------------------------------------------------------------------
// Prep: x -> fp16 hi plane. grid 8192, block 256 (4 floats/thread)
// ---------------------------------------------------------------------------
__global__ void __launch_bounds__(256) prep_x_kernel(const float* __restrict__ in)
{
    size_t i = (size_t)blockIdx.x * 256 + threadIdx.x;
    float4 v = ((const float4*)in)[i];
    uint2 H;
    H.x = packh2(v.x, v.y);
    H.y = packh2(v.z, v.w);
    ((uint2*)g_xh)[i] = H;
}

// ---------------------------------------------------------------------------
// Prep: transpose + fp16 split W. grid (32, 32, 3), block (32, 8)
// ---------------------------------------------------------------------------
__global__ void __launch_bounds__(256) prep_w_kernel(
    const float* __restrict__ WQ, const float* __restrict__ WK,
    const float* __restrict__ WV)
{
    __shared__ float t[32][33];
    const float* W = (blockIdx.z == 0) ? WQ : (blockIdx.z == 1) ? WK : WV;
    const int n0 = blockIdx.x * 32, k0 = blockIdx.y * 32;
    const int tx = threadIdx.x, ty = threadIdx.y;
#pragma unroll
    for (int j = 0; j < 32; j += 8)
        t[ty + j][tx] = W[(size_t)(k0 + ty + j) * DD + n0 + tx];
    __syncthreads();
    __half* oh = g_Wth + (size_t)blockIdx.z * DD * DD;
    __half* ol = g_Wtl + (size_t)blockIdx.z * DD * DD;
#pragma unroll
    for (int j = 0; j < 32; j += 8) {
        float v = t[tx][ty + j];
        __half h = __float2half_rn(v);
        __half l = __float2half_rn(v - __half2float(h));
        size_t o = (size_t)(n0 + ty + j) * DD + k0 + tx;
        oh[o] = h;
        ol[o] = l;
    }
}

// ---------------------------------------------------------------------------
// Softmax: fp32 P row -> fp16 hi plane, zero-padded to 128-tile edge.
// Threads beyond the causal extent skip global loads entirely.
// grid 8192, block 256
// ---------------------------------------------------------------------------
__global__ void __launch_bounds__(256) softmax_kernel()
{
    const int row = blockIdx.x;
    const int b = row >> 11;
    const int i = row & 2047;
    const float* p = g_P + ((size_t)b * SS + i) * SS;
    __half* ph = g_Ph + ((size_t)b * SS + i) * SS;
    const int L = i + 1;
    const int E = ((i >> 7) + 1) << 7;
    const int tid = threadIdx.x;
    const int base = tid * 8;
    const bool active = (base < E);

    __shared__ float red[256];

    float vals[8];
    float m = -INFINITY;
    if (active) {
        float4 v0 = ((const float4*)p)[tid * 2];
        float4 v1 = ((const float4*)p)[tid * 2 + 1];
        vals[0] = v0.x; vals[1] = v0.y; vals[2] = v0.z; vals[3] = v0.w;
        vals[4] = v1.x; vals[5] = v1.y; vals[6] = v1.z; vals[7] = v1.w;
#pragma unroll
        for (int u = 0; u < 8; u++) {
            if (base + u >= L) vals[u] = -INFINITY;
            m = fmaxf(m, vals[u]);
        }
    } else {
#pragma unroll
        for (int u = 0; u < 8; u++) vals[u] = -INFINITY;
    }
    red[tid] = m;
    __syncthreads();
    for (int s = 128; s > 0; s >>= 1) {
        if (tid < s) red[tid] = fmaxf(red[tid], red[tid + s]);
        __syncthreads();
    }
    m = red[0];
    __syncthreads();

    float sum = 0.f;
    if (active) {
#pragma unroll
        for (int u = 0; u < 8; u++) {
            vals[u] = (base + u < L) ? expf(vals[u] - m) : 0.f;
            sum += vals[u];
        }
    }
    red[tid] = sum;
    __syncthreads();
    for (int s = 128; s > 0; s >>= 1) {
        if (tid < s) red[tid] += red[tid + s];
        __syncthreads();
    }
    const float inv = 1.f / red[0];

    if (active) {
        uint4 H;
        H.x = packh2(vals[0] * inv, vals[1] * inv);
        H.y = packh2(vals[2] * inv, vals[3] * inv);
        H.z = packh2(vals[4] * inv, vals[5] * inv);
        H.w = packh2(vals[6] * inv, vals[7] * inv);
        *(uint4*)(ph + base) = H;
    }
}

// ---------------------------------------------------------------------------
extern "C" void kernel_launch(void* const* d_in, const int* in_sizes, int n_in,
                              void* d_out, int out_size)
{
    (void)in_sizes; (void)n_in; (void)out_size;
    const float* x  = (const float*)d_in[0];
    const float* WQ = (const float*)d_in[1];
    const float* WK = (const float*)d_in[2];
    const float* WV = (const float*)d_in[3];
    float* out = (float*)d_out;

    cudaFuncSetAttribute(qkv_gemm,    cudaFuncAttributeMaxDynamicSharedMemorySize, SM_TOT);
    cudaFuncSetAttribute(scores_gemm, cudaFuncAttributeMaxDynamicSharedMemorySize, SM_TOT);
    cudaFuncSetAttribute(pv_gemm,     cudaFuncAttributeMaxDynamicSharedMemorySize, SM_TOT);

    prep_x_kernel<<<8192, 256>>>(x);
    prep_w_kernel<<<dim3(32, 32, 3), dim3(32, 8)>>>(WQ, WK, WV);
    qkv_gemm<<<dim3(8, 64, 3), 256, SM_TOT>>>();
    scores_gemm<<<dim3(136, 4), 256, SM_TOT>>>();
    softmax_kernel<<<8192, 256>>>();
    pv_gemm<<<dim3(8, 16, 4), 256, SM_TOT>>>(out);
}

// round 10
// speedup vs baseline: 1.5038x; 1.2614x over previous
#include <cuda_runtime.h>
#include <cuda_fp16.h>
#include <math.h>
#include <stdint.h>

#define BB 4
#define SS 2048
#define DD 1024
#define MT (BB*SS)   // 8192

// ---------------------------------------------------------------------------
// Scratch (device globals)
// ---------------------------------------------------------------------------
__device__ __align__(16) __half g_xh [(size_t)MT*DD];                 // A of QKV
__device__ __align__(16) __half g_Wth[(size_t)3*DD*DD], g_Wtl[(size_t)3*DD*DD];
__device__ __align__(16) __half g_Qh [(size_t)MT*DD];                 // A of scores
__device__ __align__(16) __half g_Kh [(size_t)MT*DD];                 // B of scores
__device__ __align__(16) __half g_Vth[(size_t)BB*DD*SS];              // B of PV
__device__ __align__(16) float  g_P  [(size_t)BB*SS*SS];
__device__ __align__(16) __half g_Ph [(size_t)BB*SS*SS];              // A of PV

// ---------------------------------------------------------------------------
// Helpers
// ---------------------------------------------------------------------------
__device__ __forceinline__ uint32_t smem_u32(const void* p) {
    uint32_t a;
    asm("{ .reg .u64 t; cvta.to.shared.u64 t, %1; cvt.u32.u64 %0, t; }"
        : "=r"(a) : "l"(p));
    return a;
}

#define SWZ(o) ((uint32_t)(o) ^ ((((uint32_t)(o)) >> 3) & 0x70))

#define CP_ASYNC(dst, src) \
    asm volatile("cp.async.cg.shared.global [%0], [%1], 16;" \
                 :: "r"(dst), "l"(__cvta_generic_to_global(src)))
#define CP_COMMIT() asm volatile("cp.async.commit_group;")
#define CP_WAIT1()  asm volatile("cp.async.wait_group 1;")
#define CP_WAIT0()  asm volatile("cp.async.wait_group 0;")

#define LDM_X4(r, addr) \
    asm volatile("ldmatrix.sync.aligned.m8n8.x4.shared.b16 {%0,%1,%2,%3}, [%4];" \
        : "=r"((r)[0]), "=r"((r)[1]), "=r"((r)[2]), "=r"((r)[3]) : "r"(addr))

#define MMA_F16(d, a, b0v, b1v) \
    asm volatile("mma.sync.aligned.m16n8k16.row.col.f32.f16.f16.f32 " \
        "{%0,%1,%2,%3}, {%4,%5,%6,%7}, {%8,%9}, {%0,%1,%2,%3};" \
        : "+f"((d)[0]), "+f"((d)[1]), "+f"((d)[2]), "+f"((d)[3]) \
        : "r"((a)[0]), "r"((a)[1]), "r"((a)[2]), "r"((a)[3]), "r"(b0v), "r"(b1v))

__device__ __forceinline__ uint32_t packh2(float a, float b) {
    __half2 h = __floats2half2_rn(a, b);
    return *(uint32_t*)&h;
}
__device__ __forceinline__ void split2(float a, float b, uint32_t& hi, uint32_t& lo) {
    __half ha = __float2half_rn(a), hb = __float2half_rn(b);
    __half la = __float2half_rn(a - __half2float(ha));
    __half lb = __float2half_rn(b - __half2float(hb));
    hi = (uint32_t)*(uint16_t*)&ha | ((uint32_t)*(uint16_t*)&hb << 16);
    lo = (uint32_t)*(uint16_t*)&la | ((uint32_t)*(uint16_t*)&lb << 16);
}

// ---------------------------------------------------------------------------
// SMEM layouts (both fit in 96KB -> 2 CTAs/SM):
//   2-term (QKV):  stage = A(16K)+BH(16K)+BL(16K) = 48KB x 2 stages
//   1-term (S/PV): stage = A(16K)+B(16K)         = 32KB x 3 stages
// ---------------------------------------------------------------------------
#define OFF_A  0
#define OFF_BH 16384
#define OFF_BL 32768
#define STG2   49152
#define OFF1_B 16384
#define STG1   32768
#define SM_TOT 98304

// transpose-staging (epilogue reuse): 128 rows x 130 half = 260B rows
#define TRROW 260
#define TRH   0

// ===========================================================================
// 2-term GEMM (QKV): acc += A*(Bh+Bl), 2-stage pipeline (proven R7 form).
// ===========================================================================
__device__ __forceinline__ void load_chunk2(
    uint32_t stg,
    const __half* __restrict__ A, int lda,
    const __half* __restrict__ Bh, const __half* __restrict__ Bl, int ldb,
    int k0, int tid)
{
#pragma unroll
    for (int i = 0; i < 4; ++i) {
        int u = tid + i * 256, row = u >> 3, ch = u & 7;
        uint32_t off = SWZ(row * 128 + ch * 16);
        size_t ga = (size_t)row * lda + k0 + ch * 8;
        size_t gb = (size_t)row * ldb + k0 + ch * 8;
        CP_ASYNC(stg + OFF_A  + off, A  + ga);
        CP_ASYNC(stg + OFF_BH + off, Bh + gb);
        CP_ASYNC(stg + OFF_BL + off, Bl + gb);
    }
}

__device__ __forceinline__ void compute_chunk2(
    uint32_t stg, int wm, int wn, int lane, float (&acc)[4][4][4])
{
    const int rsel = lane & 15;
    const int csel = lane >> 4;
#pragma unroll
    for (int ks = 0; ks < 4; ++ks) {
        uint32_t ah[4][4], bh[2][4], bl[2][4];
#pragma unroll
        for (int i = 0; i < 4; ++i) {
            uint32_t off = SWZ((wm * 64 + i * 16 + rsel) * 128 + (ks * 2 + csel) * 16);
            LDM_X4(ah[i], stg + OFF_A + off);
        }
#pragma unroll
        for (int j2 = 0; j2 < 2; ++j2) {
            uint32_t off = SWZ((wn * 32 + j2 * 16 + rsel) * 128 + (ks * 2 + csel) * 16);
            LDM_X4(bh[j2], stg + OFF_BH + off);
            LDM_X4(bl[j2], stg + OFF_BL + off);
        }
#pragma unroll
        for (int i = 0; i < 4; ++i) {
#pragma unroll
            for (int j = 0; j < 4; ++j) {
                const int j2 = j >> 1, s = j & 1;
                MMA_F16(acc[i][j], ah[i], bh[j2][s], bh[j2][s + 2]);
                MMA_F16(acc[i][j], ah[i], bl[j2][s], bl[j2][s + 2]);
            }
        }
    }
}

__device__ __forceinline__ void gemm_2t(
    const __half* __restrict__ A, int lda,
    const __half* __restrict__ Bh, const __half* __restrict__ Bl, int ldb,
    int nCh, float (&acc)[4][4][4], uint32_t sb, int tid)
{
    const int lane = tid & 31, w = tid >> 5;
    const int wm = w & 1, wn = w >> 1;

#pragma unroll
    for (int i = 0; i < 4; ++i)
#pragma unroll
        for (int j = 0; j < 4; ++j)
#pragma unroll
            for (int q = 0; q < 4; ++q) acc[i][j][q] = 0.f;

    load_chunk2(sb, A, lda, Bh, Bl, ldb, 0, tid);
    CP_COMMIT();

    for (int c = 0; c < nCh; ++c) {
        CP_WAIT0();
        __syncthreads();
        if (c + 1 < nCh) {
            load_chunk2(sb + ((c + 1) & 1) * STG2, A, lda, Bh, Bl, ldb,
                        (c + 1) * 64, tid);
            CP_COMMIT();
        }
        compute_chunk2(sb + (c & 1) * STG2, wm, wn, lane, acc);
    }
}

// ===========================================================================
// 1-term GEMM (scores/PV): acc += A*B, 3-stage pipeline.
// ===========================================================================
__device__ __forceinline__ void load_chunk1(
    uint32_t stg,
    const __half* __restrict__ A, int lda,
    const __half* __restrict__ B, int ldb,
    int k0, int tid)
{
#pragma unroll
    for (int i = 0; i < 4; ++i) {
        int u = tid + i * 256, row = u >> 3, ch = u & 7;
        uint32_t off = SWZ(row * 128 + ch * 16);
        CP_ASYNC(stg + OFF_A  + off, A + (size_t)row * lda + k0 + ch * 8);
        CP_ASYNC(stg + OFF1_B + off, B + (size_t)row * ldb + k0 + ch * 8);
    }
}

__device__ __forceinline__ void compute_chunk1(
    uint32_t stg, int wm, int wn, int lane, float (&acc)[4][4][4])
{
    const int rsel = lane & 15;
    const int csel = lane >> 4;
#pragma unroll
    for (int ks = 0; ks < 4; ++ks) {
        uint32_t ah[4][4], bh[2][4];
#pragma unroll
        for (int i = 0; i < 4; ++i) {
            uint32_t off = SWZ((wm * 64 + i * 16 + rsel) * 128 + (ks * 2 + csel) * 16);
            LDM_X4(ah[i], stg + OFF_A + off);
        }
#pragma unroll
        for (int j2 = 0; j2 < 2; ++j2) {
            uint32_t off = SWZ((wn * 32 + j2 * 16 + rsel) * 128 + (ks * 2 + csel) * 16);
            LDM_X4(bh[j2], stg + OFF1_B + off);
        }
#pragma unroll
        for (int i = 0; i < 4; ++i)
#pragma unroll
            for (int j = 0; j < 4; ++j)
                MMA_F16(acc[i][j], ah[i], bh[j >> 1][j & 1], bh[j >> 1][(j & 1) + 2]);
    }
}

__device__ __forceinline__ void gemm_1t(
    const __half* __restrict__ A, int lda,
    const __half* __restrict__ B, int ldb,
    int nCh, float (&acc)[4][4][4], uint32_t sb, int tid)
{
    const int lane = tid & 31, w = tid >> 5;
    const int wm = w & 1, wn = w >> 1;

#pragma unroll
    for (int i = 0; i < 4; ++i)
#pragma unroll
        for (int j = 0; j < 4; ++j)
#pragma unroll
            for (int q = 0; q < 4; ++q) acc[i][j][q] = 0.f;

    // prefetch 2 chunks (nCh >= 2 always)
    load_chunk1(sb + 0 * STG1, A, lda, B, ldb, 0, tid);
    CP_COMMIT();
    load_chunk1(sb + 1 * STG1, A, lda, B, ldb, 64, tid);
    CP_COMMIT();

    int slot = 0;
    for (int c = 0; c < nCh; ++c) {
        if (c + 1 < nCh) { CP_WAIT1(); } else { CP_WAIT0(); }
        __syncthreads();
        if (c + 2 < nCh) {
            int ns = slot + 2; if (ns >= 3) ns -= 3;
            load_chunk1(sb + ns * STG1, A, lda, B, ldb, (c + 2) * 64, tid);
            CP_COMMIT();
        }
        compute_chunk1(sb + slot * STG1, wm, wn, lane, acc);
        if (++slot == 3) slot = 0;
    }
}

// ---------------------------------------------------------------------------
// 1) QKV GEMM: z=0->Q (fp16 hi), z=1->K (fp16 hi),
//    z=2->V transposed fp16 hi (fused transpose via smem). grid (8, 64, 3)
// ---------------------------------------------------------------------------
__global__ void __launch_bounds__(256, 2) qkv_gemm()
{
    extern __shared__ char smem[];
    const uint32_t sb = smem_u32(smem);
    const int tid = threadIdx.x, lane = tid & 31, w = tid >> 5;
    const int z = blockIdx.z;
    const int n0 = blockIdx.x * 128;
    const int m0 = blockIdx.y * 128;

    float acc[4][4][4];
    gemm_2t(g_xh + (size_t)m0 * DD, DD,
            g_Wth + (size_t)z * DD * DD + (size_t)n0 * DD,
            g_Wtl + (size_t)z * DD * DD + (size_t)n0 * DD, DD,
            16, acc, sb, tid);

    const int tg = lane >> 2, t4 = lane & 3;
    const int wm = w & 1, wn = w >> 1;

    if (z == 2) {
        // Fused V transpose (hi plane only).
        __syncthreads();
#pragma unroll
        for (int i = 0; i < 4; ++i) {
#pragma unroll
            for (int j = 0; j < 4; ++j) {
                const int rl = wm * 64 + i * 16 + tg;
                const int cl = wn * 32 + j * 8 + t4 * 2;
                *(uint32_t*)(smem + TRH + rl * TRROW + cl * 2) =
                    packh2(acc[i][j][0], acc[i][j][1]);
                *(uint32_t*)(smem + TRH + (rl + 8) * TRROW + cl * 2) =
                    packh2(acc[i][j][2], acc[i][j][3]);
            }
        }
        __syncthreads();
        const int b = m0 >> 11, s0r = m0 & 2047;
        const int d = tid >> 1, sh = tid & 1;
        __half* dstH = g_Vth + ((size_t)b * DD + n0 + d) * SS + s0r + sh * 64;
#pragma unroll
        for (int g = 0; g < 8; ++g) {
            uint32_t wh[4];
#pragma unroll
            for (int e = 0; e < 4; ++e) {
                const int s = sh * 64 + g * 8 + e * 2;
                uint32_t h0 = *(uint16_t*)(smem + TRH + s * TRROW + d * 2);
                uint32_t h1 = *(uint16_t*)(smem + TRH + (s + 1) * TRROW + d * 2);
                wh[e] = h0 | (h1 << 16);
            }
            *(uint4*)(dstH + g * 8) = make_uint4(wh[0], wh[1], wh[2], wh[3]);
        }
        return;
    }

    __half* dst = (z == 0) ? g_Qh : g_Kh;
#pragma unroll
    for (int i = 0; i < 4; ++i) {
#pragma unroll
        for (int j = 0; j < 4; ++j) {
            const int r = m0 + wm * 64 + i * 16 + tg;
            const int c = n0 + wn * 32 + j * 8 + t4 * 2;
            *(uint32_t*)(dst + (size_t)r * DD + c) =
                packh2(acc[i][j][0], acc[i][j][1]);
            *(uint32_t*)(dst + (size_t)(r + 8) * DD + c) =
                packh2(acc[i][j][2], acc[i][j][3]);
        }
    }
}

// ---------------------------------------------------------------------------
// 2) Scores: P = scale * Q @ K^T (1-term fp16), causal tiles. grid (136, 4)
// ---------------------------------------------------------------------------
__global__ void __launch_bounds__(256, 2) scores_gemm()
{
    const int t = blockIdx.x, b = blockIdx.y;
    int it = (int)floorf((sqrtf(8.f * (float)t + 1.f) - 1.f) * 0.5f);
    while ((it + 1) * (it + 2) / 2 <= t) ++it;
    while (it * (it + 1) / 2 > t) --it;
    const int jt = t - it * (it + 1) / 2;

    extern __shared__ char smem[];
    const uint32_t sb = smem_u32(smem);
    const int tid = threadIdx.x, lane = tid & 31, w = tid >> 5;

    float acc[4][4][4];
    gemm_1t(g_Qh + ((size_t)b * SS + it * 128) * DD, DD,
            g_Kh + ((size_t)b * SS + jt * 128) * DD, DD,
            16, acc, sb, tid);

    const int tg = lane >> 2, t4 = lane & 3;
    const int wm = w & 1, wn = w >> 1;
    const float scale = 0.03125f;  // 1/sqrt(1024)
#pragma unroll
    for (int i = 0; i < 4; ++i) {
#pragma unroll
        for (int j = 0; j < 4; ++j) {
            const int r = it * 128 + wm * 64 + i * 16 + tg;
            const int c = jt * 128 + wn * 32 + j * 8 + t4 * 2;
            float* base = g_P + (size_t)b * SS * SS;
            *(float2*)(base + (size_t)r * SS + c) =
                make_float2(acc[i][j][0] * scale, acc[i][j][1] * scale);
            *(float2*)(base + (size_t)(r + 8) * SS + c) =
                make_float2(acc[i][j][2] * scale, acc[i][j][3] * scale);
        }
    }
}

// ---------------------------------------------------------------------------
// 3) PV: O = P @ V (1-term fp16). Heavy row-blocks first. grid (8, 16, 4)
// ---------------------------------------------------------------------------
__global__ void __launch_bounds__(256, 2) pv_gemm(float* __restrict__ out)
{
    extern __shared__ char smem[];
    const uint32_t sb = smem_u32(smem);
    const int tid = threadIdx.x, lane = tid & 31, w = tid >> 5;
    const int n0 = blockIdx.x * 128;
    const int it = 15 - blockIdx.y;   // heavy-first
    const int b = blockIdx.z;

    float acc[4][4][4];
    gemm_1t(g_Ph + ((size_t)b * SS + it * 128) * SS, SS,
            g_Vth + ((size_t)b * DD + n0) * SS, SS,
            (it + 1) * 2, acc, sb, tid);

    const int tg = lane >> 2, t4 = lane & 3;
    const int wm = w & 1, wn = w >> 1;
#pragma unroll
    for (int i = 0; i < 4; ++i) {
#pragma unroll
        for (int j = 0; j < 4; ++j) {
            const size_t r = (size_t)b * SS + it * 128 + wm * 64 + i * 16 + tg;
            const int c = n0 + wn * 32 + j * 8 + t4 * 2;
            *(float2*)(out + r * DD + c) = make_float2(acc[i][j][0], acc[i][j][1]);
            *(float2*)(out + (r + 8) * DD + c) = make_float2(acc[i][j][2], acc[i][j][3]);
        }
    }
}

// ---------------------------------------------------------------------------
// Prep: x -> fp16 hi plane. grid 8192, block 256
// ---------------------------------------------------------------------------
__global__ void __launch_bounds__(256) prep_x_kernel(const float* __restrict__ in)
{
    size_t i = (size_t)blockIdx.x * 256 + threadIdx.x;
    float4 v = ((const float4*)in)[i];
    uint2 H;
    H.x = packh2(v.x, v.y);
    H.y = packh2(v.z, v.w);
    ((uint2*)g_xh)[i] = H;
}

// ---------------------------------------------------------------------------
// Prep: transpose + fp16 split W. grid (32, 32, 3), block (32, 8)
// ---------------------------------------------------------------------------
__global__ void __launch_bounds__(256) prep_w_kernel(
    const float* __restrict__ WQ, const float* __restrict__ WK,
    const float* __restrict__ WV)
{
    __shared__ float t[32][33];
    const float* W = (blockIdx.z == 0) ? WQ : (blockIdx.z == 1) ? WK : WV;
    const int n0 = blockIdx.x * 32, k0 = blockIdx.y * 32;
    const int tx = threadIdx.x, ty = threadIdx.y;
#pragma unroll
    for (int j = 0; j < 32; j += 8)
        t[ty + j][tx] = W[(size_t)(k0 + ty + j) * DD + n0 + tx];
    __syncthreads();
    __half* oh = g_Wth + (size_t)blockIdx.z * DD * DD;
    __half* ol = g_Wtl + (size_t)blockIdx.z * DD * DD;
#pragma unroll
    for (int j = 0; j < 32; j += 8) {
        float v = t[tx][ty + j];
        __half h = __float2half_rn(v);
        __half l = __float2half_rn(v - __half2float(h));
        size_t o = (size_t)(n0 + ty + j) * DD + k0 + tx;
        oh[o] = h;
        ol[o] = l;
    }
}

// ---------------------------------------------------------------------------
// Softmax: fp32 P row -> fp16 hi plane, zero-padded to 128-tile edge.
// Threads beyond the causal extent skip global loads. grid 8192, block 256
// ---------------------------------------------------------------------------
__global__ void __launch_bounds__(256) softmax_kernel()
{
    const int row = blockIdx.x;
    const int b = row >> 11;
    const int i = row & 2047;
    const float* p = g_P + ((size_t)b * SS + i) * SS;
    __half* ph = g_Ph + ((size_t)b * SS + i) * SS;
    const int L = i + 1;
    const int E = ((i >> 7) + 1) << 7;
    const int tid = threadIdx.x;
    const int base = tid * 8;
    const bool active = (base < E);

    __shared__ float red[256];

    float vals[8];
    float m = -INFINITY;
    if (active) {
        float4 v0 = ((const float4*)p)[tid * 2];
        float4 v1 = ((const float4*)p)[tid * 2 + 1];
        vals[0] = v0.x; vals[1] = v0.y; vals[2] = v0.z; vals[3] = v0.w;
        vals[4] = v1.x; vals[5] = v1.y; vals[6] = v1.z; vals[7] = v1.w;
#pragma unroll
        for (int u = 0; u < 8; u++) {
            if (base + u >= L) vals[u] = -INFINITY;
            m = fmaxf(m, vals[u]);
        }
    } else {
#pragma unroll
        for (int u = 0; u < 8; u++) vals[u] = -INFINITY;
    }
    red[tid] = m;
    __syncthreads();
    for (int s = 128; s > 0; s >>= 1) {
        if (tid < s) red[tid] = fmaxf(red[tid], red[tid + s]);
        __syncthreads();
    }
    m = red[0];
    __syncthreads();

    float sum = 0.f;
    if (active) {
#pragma unroll
        for (int u = 0; u < 8; u++) {
            vals[u] = (base + u < L) ? expf(vals[u] - m) : 0.f;
            sum += vals[u];
        }
    }
    red[tid] = sum;
    __syncthreads();
    for (int s = 128; s > 0; s >>= 1) {
        if (tid < s) red[tid] += red[tid + s];
        __syncthreads();
    }
    const float inv = 1.f / red[0];

    if (active) {
        uint4 H;
        H.x = packh2(vals[0] * inv, vals[1] * inv);
        H.y = packh2(vals[2] * inv, vals[3] * inv);
        H.z = packh2(vals[4] * inv, vals[5] * inv);
        H.w = packh2(vals[6] * inv, vals[7] * inv);
        *(uint4*)(ph + base) = H;
    }
}

// ---------------------------------------------------------------------------
extern "C" void kernel_launch(void* const* d_in, const int* in_sizes, int n_in,
                              void* d_out, int out_size)
{
    (void)in_sizes; (void)n_in; (void)out_size;
    const float* x  = (const float*)d_in[0];
    const float* WQ = (const float*)d_in[1];
    const float* WK = (const float*)d_in[2];
    const float* WV = (const float*)d_in[3];
    float* out = (float*)d_out;

    cudaFuncSetAttribute(qkv_gemm,    cudaFuncAttributeMaxDynamicSharedMemorySize, SM_TOT);
    cudaFuncSetAttribute(scores_gemm, cudaFuncAttributeMaxDynamicSharedMemorySize, SM_TOT);
    cudaFuncSetAttribute(pv_gemm,     cudaFuncAttributeMaxDynamicSharedMemorySize, SM_TOT);

    prep_x_kernel<<<8192, 256>>>(x);
    prep_w_kernel<<<dim3(32, 32, 3), dim3(32, 8)>>>(WQ, WK, WV);
    qkv_gemm<<<dim3(8, 64, 3), 256, SM_TOT>>>();
    scores_gemm<<<dim3(136, 4), 256, SM_TOT>>>();
    softmax_kernel<<<8192, 256>>>();
    pv_gemm<<<dim3(8, 16, 4), 256, SM_TOT>>>(out);
}

// round 11
// speedup vs baseline: 1.5373x; 1.0223x over previous
#include <cuda_runtime.h>
#include <cuda_fp16.h>
#include <math.h>
#include <stdint.h>

#define BB 4
#define SS 2048
#define DD 1024
#define MT (BB*SS)   // 8192

// ---------------------------------------------------------------------------
// Scratch (device globals)
// ---------------------------------------------------------------------------
__device__ __align__(16) __half g_xh [(size_t)MT*DD];                 // A of QKV
__device__ __align__(16) __half g_Wth[(size_t)3*DD*DD], g_Wtl[(size_t)3*DD*DD];
__device__ __align__(16) __half g_Qh [(size_t)MT*DD];                 // A of scores
__device__ __align__(16) __half g_Kh [(size_t)MT*DD];                 // B of scores
__device__ __align__(16) __half g_Vth[(size_t)BB*DD*SS];              // B of PV
__device__ __align__(16) __half g_Ph [(size_t)BB*SS*SS];              // Pexp (unnormalized)
__device__ __align__(16) float  g_rs [MT];                            // row sums

// ---------------------------------------------------------------------------
// Helpers
// ---------------------------------------------------------------------------
__device__ __forceinline__ uint32_t smem_u32(const void* p) {
    uint32_t a;
    asm("{ .reg .u64 t; cvta.to.shared.u64 t, %1; cvt.u32.u64 %0, t; }"
        : "=r"(a) : "l"(p));
    return a;
}

#define SWZ(o) ((uint32_t)(o) ^ ((((uint32_t)(o)) >> 3) & 0x70))

#define CP_ASYNC(dst, src) \
    asm volatile("cp.async.cg.shared.global [%0], [%1], 16;" \
                 :: "r"(dst), "l"(__cvta_generic_to_global(src)))
#define CP_COMMIT() asm volatile("cp.async.commit_group;")
#define CP_WAIT1()  asm volatile("cp.async.wait_group 1;")
#define CP_WAIT0()  asm volatile("cp.async.wait_group 0;")

#define LDM_X4(r, addr) \
    asm volatile("ldmatrix.sync.aligned.m8n8.x4.shared.b16 {%0,%1,%2,%3}, [%4];" \
        : "=r"((r)[0]), "=r"((r)[1]), "=r"((r)[2]), "=r"((r)[3]) : "r"(addr))

#define MMA_F16(d, a, b0v, b1v) \
    asm volatile("mma.sync.aligned.m16n8k16.row.col.f32.f16.f16.f32 " \
        "{%0,%1,%2,%3}, {%4,%5,%6,%7}, {%8,%9}, {%0,%1,%2,%3};" \
        : "+f"((d)[0]), "+f"((d)[1]), "+f"((d)[2]), "+f"((d)[3]) \
        : "r"((a)[0]), "r"((a)[1]), "r"((a)[2]), "r"((a)[3]), "r"(b0v), "r"(b1v))

__device__ __forceinline__ uint32_t packh2(float a, float b) {
    __half2 h = __floats2half2_rn(a, b);
    return *(uint32_t*)&h;
}

// ---------------------------------------------------------------------------
// SMEM layouts (both fit in 96KB -> 2 CTAs/SM):
//   2-term (QKV):  stage = A(16K)+BH(16K)+BL(16K) = 48KB x 2 stages
//   1-term (S/PV): stage = A(16K)+B(16K)         = 32KB x 3 stages
// ---------------------------------------------------------------------------
#define OFF_A  0
#define OFF_BH 16384
#define OFF_BL 32768
#define STG2   49152
#define OFF1_B 16384
#define STG1   32768
#define SM_TOT 98304

// transpose-staging (epilogue reuse): 128 rows x 130 half = 260B rows
#define TRROW 260
#define TRH   0

// ===========================================================================
// 2-term GEMM (QKV): acc += A*(Bh+Bl), 2-stage pipeline.
// ===========================================================================
__device__ __forceinline__ void load_chunk2(
    uint32_t stg,
    const __half* __restrict__ A, int lda,
    const __half* __restrict__ Bh, const __half* __restrict__ Bl, int ldb,
    int k0, int tid)
{
#pragma unroll
    for (int i = 0; i < 4; ++i) {
        int u = tid + i * 256, row = u >> 3, ch = u & 7;
        uint32_t off = SWZ(row * 128 + ch * 16);
        size_t ga = (size_t)row * lda + k0 + ch * 8;
        size_t gb = (size_t)row * ldb + k0 + ch * 8;
        CP_ASYNC(stg + OFF_A  + off, A  + ga);
        CP_ASYNC(stg + OFF_BH + off, Bh + gb);
        CP_ASYNC(stg + OFF_BL + off, Bl + gb);
    }
}

__device__ __forceinline__ void compute_chunk2(
    uint32_t stg, int wm, int wn, int lane, float (&acc)[4][4][4])
{
    const int rsel = lane & 15;
    const int csel = lane >> 4;
#pragma unroll
    for (int ks = 0; ks < 4; ++ks) {
        uint32_t ah[4][4], bh[2][4], bl[2][4];
#pragma unroll
        for (int i = 0; i < 4; ++i) {
            uint32_t off = SWZ((wm * 64 + i * 16 + rsel) * 128 + (ks * 2 + csel) * 16);
            LDM_X4(ah[i], stg + OFF_A + off);
        }
#pragma unroll
        for (int j2 = 0; j2 < 2; ++j2) {
            uint32_t off = SWZ((wn * 32 + j2 * 16 + rsel) * 128 + (ks * 2 + csel) * 16);
            LDM_X4(bh[j2], stg + OFF_BH + off);
            LDM_X4(bl[j2], stg + OFF_BL + off);
        }
#pragma unroll
        for (int i = 0; i < 4; ++i) {
#pragma unroll
            for (int j = 0; j < 4; ++j) {
                const int j2 = j >> 1, s = j & 1;
                MMA_F16(acc[i][j], ah[i], bh[j2][s], bh[j2][s + 2]);
                MMA_F16(acc[i][j], ah[i], bl[j2][s], bl[j2][s + 2]);
            }
        }
    }
}

__device__ __forceinline__ void gemm_2t(
    const __half* __restrict__ A, int lda,
    const __half* __restrict__ Bh, const __half* __restrict__ Bl, int ldb,
    int nCh, float (&acc)[4][4][4], uint32_t sb, int tid)
{
    const int lane = tid & 31, w = tid >> 5;
    const int wm = w & 1, wn = w >> 1;

#pragma unroll
    for (int i = 0; i < 4; ++i)
#pragma unroll
        for (int j = 0; j < 4; ++j)
#pragma unroll
            for (int q = 0; q < 4; ++q) acc[i][j][q] = 0.f;

    load_chunk2(sb, A, lda, Bh, Bl, ldb, 0, tid);
    CP_COMMIT();

    for (int c = 0; c < nCh; ++c) {
        CP_WAIT0();
        __syncthreads();
        if (c + 1 < nCh) {
            load_chunk2(sb + ((c + 1) & 1) * STG2, A, lda, Bh, Bl, ldb,
                        (c + 1) * 64, tid);
            CP_COMMIT();
        }
        compute_chunk2(sb + (c & 1) * STG2, wm, wn, lane, acc);
    }
}

// ===========================================================================
// 1-term GEMM (scores/PV): acc += A*B, 3-stage pipeline.
// ===========================================================================
__device__ __forceinline__ void load_chunk1(
    uint32_t stg,
    const __half* __restrict__ A, int lda,
    const __half* __restrict__ B, int ldb,
    int k0, int tid)
{
#pragma unroll
    for (int i = 0; i < 4; ++i) {
        int u = tid + i * 256, row = u >> 3, ch = u & 7;
        uint32_t off = SWZ(row * 128 + ch * 16);
        CP_ASYNC(stg + OFF_A  + off, A + (size_t)row * lda + k0 + ch * 8);
        CP_ASYNC(stg + OFF1_B + off, B + (size_t)row * ldb + k0 + ch * 8);
    }
}

__device__ __forceinline__ void compute_chunk1(
    uint32_t stg, int wm, int wn, int lane, float (&acc)[4][4][4])
{
    const int rsel = lane & 15;
    const int csel = lane >> 4;
#pragma unroll
    for (int ks = 0; ks < 4; ++ks) {
        uint32_t ah[4][4], bh[2][4];
#pragma unroll
        for (int i = 0; i < 4; ++i) {
            uint32_t off = SWZ((wm * 64 + i * 16 + rsel) * 128 + (ks * 2 + csel) * 16);
            LDM_X4(ah[i], stg + OFF_A + off);
        }
#pragma unroll
        for (int j2 = 0; j2 < 2; ++j2) {
            uint32_t off = SWZ((wn * 32 + j2 * 16 + rsel) * 128 + (ks * 2 + csel) * 16);
            LDM_X4(bh[j2], stg + OFF1_B + off);
        }
#pragma unroll
        for (int i = 0; i < 4; ++i)
#pragma unroll
            for (int j = 0; j < 4; ++j)
                MMA_F16(acc[i][j], ah[i], bh[j >> 1][j & 1], bh[j >> 1][(j & 1) + 2]);
    }
}

__device__ __forceinline__ void gemm_1t(
    const __half* __restrict__ A, int lda,
    const __half* __restrict__ B, int ldb,
    int nCh, float (&acc)[4][4][4], uint32_t sb, int tid)
{
    const int lane = tid & 31, w = tid >> 5;
    const int wm = w & 1, wn = w >> 1;

#pragma unroll
    for (int i = 0; i < 4; ++i)
#pragma unroll
        for (int j = 0; j < 4; ++j)
#pragma unroll
            for (int q = 0; q < 4; ++q) acc[i][j][q] = 0.f;

    load_chunk1(sb + 0 * STG1, A, lda, B, ldb, 0, tid);
    CP_COMMIT();
    load_chunk1(sb + 1 * STG1, A, lda, B, ldb, 64, tid);
    CP_COMMIT();

    int slot = 0;
    for (int c = 0; c < nCh; ++c) {
        if (c + 1 < nCh) { CP_WAIT1(); } else { CP_WAIT0(); }
        __syncthreads();
        if (c + 2 < nCh) {
            int ns = slot + 2; if (ns >= 3) ns -= 3;
            load_chunk1(sb + ns * STG1, A, lda, B, ldb, (c + 2) * 64, tid);
            CP_COMMIT();
        }
        compute_chunk1(sb + slot * STG1, wm, wn, lane, acc);
        if (++slot == 3) slot = 0;
    }
}

// ---------------------------------------------------------------------------
// 0) Zero row-sum accumulators (graph-replay safe). grid 8, block 1024
// ---------------------------------------------------------------------------
__global__ void __launch_bounds__(1024) zero_rs()
{
    g_rs[blockIdx.x * 1024 + threadIdx.x] = 0.f;
}

// ---------------------------------------------------------------------------
// 1) QKV GEMM: z=0->Q (fp16 hi), z=1->K (fp16 hi),
//    z=2->V transposed fp16 hi (fused transpose via smem). grid (8, 64, 3)
// ---------------------------------------------------------------------------
__global__ void __launch_bounds__(256, 2) qkv_gemm()
{
    extern __shared__ char smem[];
    const uint32_t sb = smem_u32(smem);
    const int tid = threadIdx.x, lane = tid & 31, w = tid >> 5;
    const int z = blockIdx.z;
    const int n0 = blockIdx.x * 128;
    const int m0 = blockIdx.y * 128;

    float acc[4][4][4];
    gemm_2t(g_xh + (size_t)m0 * DD, DD,
            g_Wth + (size_t)z * DD * DD + (size_t)n0 * DD,
            g_Wtl + (size_t)z * DD * DD + (size_t)n0 * DD, DD,
            16, acc, sb, tid);

    const int tg = lane >> 2, t4 = lane & 3;
    const int wm = w & 1, wn = w >> 1;

    if (z == 2) {
        // Fused V transpose (hi plane only).
        __syncthreads();
#pragma unroll
        for (int i = 0; i < 4; ++i) {
#pragma unroll
            for (int j = 0; j < 4; ++j) {
                const int rl = wm * 64 + i * 16 + tg;
                const int cl = wn * 32 + j * 8 + t4 * 2;
                *(uint32_t*)(smem + TRH + rl * TRROW + cl * 2) =
                    packh2(acc[i][j][0], acc[i][j][1]);
                *(uint32_t*)(smem + TRH + (rl + 8) * TRROW + cl * 2) =
                    packh2(acc[i][j][2], acc[i][j][3]);
            }
        }
        __syncthreads();
        const int b = m0 >> 11, s0r = m0 & 2047;
        const int d = tid >> 1, sh = tid & 1;
        __half* dstH = g_Vth + ((size_t)b * DD + n0 + d) * SS + s0r + sh * 64;
#pragma unroll
        for (int g = 0; g < 8; ++g) {
            uint32_t wh[4];
#pragma unroll
            for (int e = 0; e < 4; ++e) {
                const int s = sh * 64 + g * 8 + e * 2;
                uint32_t h0 = *(uint16_t*)(smem + TRH + s * TRROW + d * 2);
                uint32_t h1 = *(uint16_t*)(smem + TRH + (s + 1) * TRROW + d * 2);
                wh[e] = h0 | (h1 << 16);
            }
            *(uint4*)(dstH + g * 8) = make_uint4(wh[0], wh[1], wh[2], wh[3]);
        }
        return;
    }

    __half* dst = (z == 0) ? g_Qh : g_Kh;
#pragma unroll
    for (int i = 0; i < 4; ++i) {
#pragma unroll
        for (int j = 0; j < 4; ++j) {
            const int r = m0 + wm * 64 + i * 16 + tg;
            const int c = n0 + wn * 32 + j * 8 + t4 * 2;
            *(uint32_t*)(dst + (size_t)r * DD + c) =
                packh2(acc[i][j][0], acc[i][j][1]);
            *(uint32_t*)(dst + (size_t)(r + 8) * DD + c) =
                packh2(acc[i][j][2], acc[i][j][3]);
        }
    }
}

// ---------------------------------------------------------------------------
// 2) Scores+exp: Pexp = exp(scale * Q @ K^T) with causal mask, fp16 out,
//    per-row sums accumulated to g_rs via atomics. grid (136, 4)
// ---------------------------------------------------------------------------
__global__ void __launch_bounds__(256, 2) scores_gemm()
{
    const int t = blockIdx.x, b = blockIdx.y;
    int it = (int)floorf((sqrtf(8.f * (float)t + 1.f) - 1.f) * 0.5f);
    while ((it + 1) * (it + 2) / 2 <= t) ++it;
    while (it * (it + 1) / 2 > t) --it;
    const int jt = t - it * (it + 1) / 2;

    extern __shared__ char smem[];
    const uint32_t sb = smem_u32(smem);
    const int tid = threadIdx.x, lane = tid & 31, w = tid >> 5;

    float acc[4][4][4];
    gemm_1t(g_Qh + ((size_t)b * SS + it * 128) * DD, DD,
            g_Kh + ((size_t)b * SS + jt * 128) * DD, DD,
            16, acc, sb, tid);

    const int tg = lane >> 2, t4 = lane & 3;
    const int wm = w & 1, wn = w >> 1;
    const float scale = 0.03125f;  // 1/sqrt(1024)
    __half* base = g_Ph + (size_t)b * SS * SS;
    float* rs = g_rs + (size_t)b * SS;

#pragma unroll
    for (int i = 0; i < 4; ++i) {
        const int r0 = it * 128 + wm * 64 + i * 16 + tg;
        const int r1 = r0 + 8;
        float sum0 = 0.f, sum1 = 0.f;
#pragma unroll
        for (int j = 0; j < 4; ++j) {
            const int c = jt * 128 + wn * 32 + j * 8 + t4 * 2;
            float e0 = (c     <= r0) ? __expf(acc[i][j][0] * scale) : 0.f;
            float e1 = (c + 1 <= r0) ? __expf(acc[i][j][1] * scale) : 0.f;
            float e2 = (c     <= r1) ? __expf(acc[i][j][2] * scale) : 0.f;
            float e3 = (c + 1 <= r1) ? __expf(acc[i][j][3] * scale) : 0.f;
            *(uint32_t*)(base + (size_t)r0 * SS + c) = packh2(e0, e1);
            *(uint32_t*)(base + (size_t)r1 * SS + c) = packh2(e2, e3);
            sum0 += e0 + e1;
            sum1 += e2 + e3;
        }
        sum0 += __shfl_xor_sync(0xffffffffu, sum0, 1);
        sum0 += __shfl_xor_sync(0xffffffffu, sum0, 2);
        sum1 += __shfl_xor_sync(0xffffffffu, sum1, 1);
        sum1 += __shfl_xor_sync(0xffffffffu, sum1, 2);
        if (t4 == 0) {
            atomicAdd(rs + r0, sum0);
            atomicAdd(rs + r1, sum1);
        }
    }
}

// ---------------------------------------------------------------------------
// 3) PV: O = (Pexp @ V) / rowsum. Heavy row-blocks first. grid (8, 16, 4)
// ---------------------------------------------------------------------------
__global__ void __launch_bounds__(256, 2) pv_gemm(float* __restrict__ out)
{
    extern __shared__ char smem[];
    const uint32_t sb = smem_u32(smem);
    const int tid = threadIdx.x, lane = tid & 31, w = tid >> 5;
    const int n0 = blockIdx.x * 128;
    const int it = 15 - blockIdx.y;   // heavy-first
    const int b = blockIdx.z;

    float acc[4][4][4];
    gemm_1t(g_Ph + ((size_t)b * SS + it * 128) * SS, SS,
            g_Vth + ((size_t)b * DD + n0) * SS, SS,
            (it + 1) * 2, acc, sb, tid);

    const int tg = lane >> 2, t4 = lane & 3;
    const int wm = w & 1, wn = w >> 1;
#pragma unroll
    for (int i = 0; i < 4; ++i) {
        const int rr = it * 128 + wm * 64 + i * 16 + tg;
        const float inv0 = 1.f / g_rs[(size_t)b * SS + rr];
        const float inv1 = 1.f / g_rs[(size_t)b * SS + rr + 8];
        const size_t r = (size_t)b * SS + rr;
#pragma unroll
        for (int j = 0; j < 4; ++j) {
            const int c = n0 + wn * 32 + j * 8 + t4 * 2;
            *(float2*)(out + r * DD + c) =
                make_float2(acc[i][j][0] * inv0, acc[i][j][1] * inv0);
            *(float2*)(out + (r + 8) * DD + c) =
                make_float2(acc[i][j][2] * inv1, acc[i][j][3] * inv1);
        }
    }
}

// ---------------------------------------------------------------------------
// Prep: x -> fp16 hi plane. grid 8192, block 256
// ---------------------------------------------------------------------------
__global__ void __launch_bounds__(256) prep_x_kernel(const float* __restrict__ in)
{
    size_t i = (size_t)blockIdx.x * 256 + threadIdx.x;
    float4 v = ((const float4*)in)[i];
    uint2 H;
    H.x = packh2(v.x, v.y);
    H.y = packh2(v.z, v.w);
    ((uint2*)g_xh)[i] = H;
}

// ---------------------------------------------------------------------------
// Prep: transpose + fp16 split W. grid (32, 32, 3), block (32, 8)
// ---------------------------------------------------------------------------
__global__ void __launch_bounds__(256) prep_w_kernel(
    const float* __restrict__ WQ, const float* __restrict__ WK,
    const float* __restrict__ WV)
{
    __shared__ float t[32][33];
    const float* W = (blockIdx.z == 0) ? WQ : (blockIdx.z == 1) ? WK : WV;
    const int n0 = blockIdx.x * 32, k0 = blockIdx.y * 32;
    const int tx = threadIdx.x, ty = threadIdx.y;
#pragma unroll
    for (int j = 0; j < 32; j += 8)
        t[ty + j][tx] = W[(size_t)(k0 + ty + j) * DD + n0 + tx];
    __syncthreads();
    __half* oh = g_Wth + (size_t)blockIdx.z * DD * DD;
    __half* ol = g_Wtl + (size_t)blockIdx.z * DD * DD;
#pragma unroll
    for (int j = 0; j < 32; j += 8) {
        float v = t[tx][ty + j];
        __half h = __float2half_rn(v);
        __half l = __float2half_rn(v - __half2float(h));
        size_t o = (size_t)(n0 + ty + j) * DD + k0 + tx;
        oh[o] = h;
        ol[o] = l;
    }
}

// ---------------------------------------------------------------------------
extern "C" void kernel_launch(void* const* d_in, const int* in_sizes, int n_in,
                              void* d_out, int out_size)
{
    (void)in_sizes; (void)n_in; (void)out_size;
    const float* x  = (const float*)d_in[0];
    const float* WQ = (const float*)d_in[1];
    const float* WK = (const float*)d_in[2];
    const float* WV = (const float*)d_in[3];
    float* out = (float*)d_out;

    cudaFuncSetAttribute(qkv_gemm,    cudaFuncAttributeMaxDynamicSharedMemorySize, SM_TOT);
    cudaFuncSetAttribute(scores_gemm, cudaFuncAttributeMaxDynamicSharedMemorySize, SM_TOT);
    cudaFuncSetAttribute(pv_gemm,     cudaFuncAttributeMaxDynamicSharedMemorySize, SM_TOT);

    zero_rs<<<8, 1024>>>();
    prep_x_kernel<<<8192, 256>>>(x);
    prep_w_kernel<<<dim3(32, 32, 3), dim3(32, 8)>>>(WQ, WK, WV);
    qkv_gemm<<<dim3(8, 64, 3), 256, SM_TOT>>>();
    scores_gemm<<<dim3(136, 4), 256, SM_TOT>>>();
    pv_gemm<<<dim3(8, 16, 4), 256, SM_TOT>>>(out);
}

// round 12
// speedup vs baseline: 2.1514x; 1.3994x over previous
#include <cuda_runtime.h>
#include <cuda_fp16.h>
#include <math.h>
#include <stdint.h>

#define BB 4
#define SS 2048
#define DD 1024
#define MT (BB*SS)   // 8192

// ---------------------------------------------------------------------------
// Scratch (device globals) — all operands fp16 hi-plane only
// ---------------------------------------------------------------------------
__device__ __align__(16) __half g_xh [(size_t)MT*DD];                 // A of QKV
__device__ __align__(16) __half g_Wth[(size_t)3*DD*DD];               // B of QKV (transposed)
__device__ __align__(16) __half g_Qh [(size_t)MT*DD];                 // A of scores
__device__ __align__(16) __half g_Kh [(size_t)MT*DD];                 // B of scores
__device__ __align__(16) __half g_Vth[(size_t)BB*DD*SS];              // B of PV
__device__ __align__(16) __half g_Ph [(size_t)BB*SS*SS];              // Pexp (unnormalized)
__device__ __align__(16) float  g_rs [MT];                            // row sums

// ---------------------------------------------------------------------------
// Helpers
// ---------------------------------------------------------------------------
__device__ __forceinline__ uint32_t smem_u32(const void* p) {
    uint32_t a;
    asm("{ .reg .u64 t; cvta.to.shared.u64 t, %1; cvt.u32.u64 %0, t; }"
        : "=r"(a) : "l"(p));
    return a;
}

#define SWZ(o) ((uint32_t)(o) ^ ((((uint32_t)(o)) >> 3) & 0x70))

#define CP_ASYNC(dst, src) \
    asm volatile("cp.async.cg.shared.global [%0], [%1], 16;" \
                 :: "r"(dst), "l"(__cvta_generic_to_global(src)))
#define CP_COMMIT() asm volatile("cp.async.commit_group;")
#define CP_WAIT1()  asm volatile("cp.async.wait_group 1;")
#define CP_WAIT0()  asm volatile("cp.async.wait_group 0;")

#define LDM_X4(r, addr) \
    asm volatile("ldmatrix.sync.aligned.m8n8.x4.shared.b16 {%0,%1,%2,%3}, [%4];" \
        : "=r"((r)[0]), "=r"((r)[1]), "=r"((r)[2]), "=r"((r)[3]) : "r"(addr))

#define MMA_F16(d, a, b0v, b1v) \
    asm volatile("mma.sync.aligned.m16n8k16.row.col.f32.f16.f16.f32 " \
        "{%0,%1,%2,%3}, {%4,%5,%6,%7}, {%8,%9}, {%0,%1,%2,%3};" \
        : "+f"((d)[0]), "+f"((d)[1]), "+f"((d)[2]), "+f"((d)[3]) \
        : "r"((a)[0]), "r"((a)[1]), "r"((a)[2]), "r"((a)[3]), "r"(b0v), "r"(b1v))

__device__ __forceinline__ uint32_t packh2(float a, float b) {
    __half2 h = __floats2half2_rn(a, b);
    return *(uint32_t*)&h;
}

// ---------------------------------------------------------------------------
// SMEM: 1-term stage = A(16K)+B(16K) = 32KB x 3 stages = 96KB -> 2 CTAs/SM
// ---------------------------------------------------------------------------
#define OFF_A  0
#define OFF1_B 16384
#define STG1   32768
#define SM_TOT 98304

// transpose-staging (epilogue reuse): 128 rows x 130 half = 260B rows
#define TRROW 260
#define TRH   0

// ===========================================================================
// 1-term GEMM: acc += A*B, 3-stage pipeline. (sole mainloop now)
// ===========================================================================
__device__ __forceinline__ void load_chunk1(
    uint32_t stg,
    const __half* __restrict__ A, int lda,
    const __half* __restrict__ B, int ldb,
    int k0, int tid)
{
#pragma unroll
    for (int i = 0; i < 4; ++i) {
        int u = tid + i * 256, row = u >> 3, ch = u & 7;
        uint32_t off = SWZ(row * 128 + ch * 16);
        CP_ASYNC(stg + OFF_A  + off, A + (size_t)row * lda + k0 + ch * 8);
        CP_ASYNC(stg + OFF1_B + off, B + (size_t)row * ldb + k0 + ch * 8);
    }
}

__device__ __forceinline__ void compute_chunk1(
    uint32_t stg, int wm, int wn, int lane, float (&acc)[4][4][4])
{
    const int rsel = lane & 15;
    const int csel = lane >> 4;
#pragma unroll
    for (int ks = 0; ks < 4; ++ks) {
        uint32_t ah[4][4], bh[2][4];
#pragma unroll
        for (int i = 0; i < 4; ++i) {
            uint32_t off = SWZ((wm * 64 + i * 16 + rsel) * 128 + (ks * 2 + csel) * 16);
            LDM_X4(ah[i], stg + OFF_A + off);
        }
#pragma unroll
        for (int j2 = 0; j2 < 2; ++j2) {
            uint32_t off = SWZ((wn * 32 + j2 * 16 + rsel) * 128 + (ks * 2 + csel) * 16);
            LDM_X4(bh[j2], stg + OFF1_B + off);
        }
#pragma unroll
        for (int i = 0; i < 4; ++i)
#pragma unroll
            for (int j = 0; j < 4; ++j)
                MMA_F16(acc[i][j], ah[i], bh[j >> 1][j & 1], bh[j >> 1][(j & 1) + 2]);
    }
}

__device__ __forceinline__ void gemm_1t(
    const __half* __restrict__ A, int lda,
    const __half* __restrict__ B, int ldb,
    int nCh, float (&acc)[4][4][4], uint32_t sb, int tid)
{
    const int lane = tid & 31, w = tid >> 5;
    const int wm = w & 1, wn = w >> 1;

#pragma unroll
    for (int i = 0; i < 4; ++i)
#pragma unroll
        for (int j = 0; j < 4; ++j)
#pragma unroll
            for (int q = 0; q < 4; ++q) acc[i][j][q] = 0.f;

    load_chunk1(sb + 0 * STG1, A, lda, B, ldb, 0, tid);
    CP_COMMIT();
    load_chunk1(sb + 1 * STG1, A, lda, B, ldb, 64, tid);
    CP_COMMIT();

    int slot = 0;
    for (int c = 0; c < nCh; ++c) {
        if (c + 1 < nCh) { CP_WAIT1(); } else { CP_WAIT0(); }
        __syncthreads();
        if (c + 2 < nCh) {
            int ns = slot + 2; if (ns >= 3) ns -= 3;
            load_chunk1(sb + ns * STG1, A, lda, B, ldb, (c + 2) * 64, tid);
            CP_COMMIT();
        }
        compute_chunk1(sb + slot * STG1, wm, wn, lane, acc);
        if (++slot == 3) slot = 0;
    }
}

// ---------------------------------------------------------------------------
// 0) Zero row-sum accumulators (graph-replay safe). grid 8, block 1024
// ---------------------------------------------------------------------------
__global__ void __launch_bounds__(1024) zero_rs()
{
    g_rs[blockIdx.x * 1024 + threadIdx.x] = 0.f;
}

// ---------------------------------------------------------------------------
// 1) QKV GEMM (1-term): z=0->Q, z=1->K, z=2->V transposed (fused via smem).
//    grid (8, 64, 3)
// ---------------------------------------------------------------------------
__global__ void __launch_bounds__(256, 2) qkv_gemm()
{
    extern __shared__ char smem[];
    const uint32_t sb = smem_u32(smem);
    const int tid = threadIdx.x, lane = tid & 31, w = tid >> 5;
    const int z = blockIdx.z;
    const int n0 = blockIdx.x * 128;
    const int m0 = blockIdx.y * 128;

    float acc[4][4][4];
    gemm_1t(g_xh + (size_t)m0 * DD, DD,
            g_Wth + (size_t)z * DD * DD + (size_t)n0 * DD, DD,
            16, acc, sb, tid);

    const int tg = lane >> 2, t4 = lane & 3;
    const int wm = w & 1, wn = w >> 1;

    if (z == 2) {
        // Fused V transpose (hi plane only).
        __syncthreads();
#pragma unroll
        for (int i = 0; i < 4; ++i) {
#pragma unroll
            for (int j = 0; j < 4; ++j) {
                const int rl = wm * 64 + i * 16 + tg;
                const int cl = wn * 32 + j * 8 + t4 * 2;
                *(uint32_t*)(smem + TRH + rl * TRROW + cl * 2) =
                    packh2(acc[i][j][0], acc[i][j][1]);
                *(uint32_t*)(smem + TRH + (rl + 8) * TRROW + cl * 2) =
                    packh2(acc[i][j][2], acc[i][j][3]);
            }
        }
        __syncthreads();
        const int b = m0 >> 11, s0r = m0 & 2047;
        const int d = tid >> 1, sh = tid & 1;
        __half* dstH = g_Vth + ((size_t)b * DD + n0 + d) * SS + s0r + sh * 64;
#pragma unroll
        for (int g = 0; g < 8; ++g) {
            uint32_t wh[4];
#pragma unroll
            for (int e = 0; e < 4; ++e) {
                const int s = sh * 64 + g * 8 + e * 2;
                uint32_t h0 = *(uint16_t*)(smem + TRH + s * TRROW + d * 2);
                uint32_t h1 = *(uint16_t*)(smem + TRH + (s + 1) * TRROW + d * 2);
                wh[e] = h0 | (h1 << 16);
            }
            *(uint4*)(dstH + g * 8) = make_uint4(wh[0], wh[1], wh[2], wh[3]);
        }
        return;
    }

    __half* dst = (z == 0) ? g_Qh : g_Kh;
#pragma unroll
    for (int i = 0; i < 4; ++i) {
#pragma unroll
        for (int j = 0; j < 4; ++j) {
            const int r = m0 + wm * 64 + i * 16 + tg;
            const int c = n0 + wn * 32 + j * 8 + t4 * 2;
            *(uint32_t*)(dst + (size_t)r * DD + c) =
                packh2(acc[i][j][0], acc[i][j][1]);
            *(uint32_t*)(dst + (size_t)(r + 8) * DD + c) =
                packh2(acc[i][j][2], acc[i][j][3]);
        }
    }
}

// ---------------------------------------------------------------------------
// 2) Scores+exp: Pexp = exp(scale * Q @ K^T) with causal mask, fp16 out,
//    per-row sums accumulated to g_rs via atomics. grid (136, 4)
// ---------------------------------------------------------------------------
__global__ void __launch_bounds__(256, 2) scores_gemm()
{
    const int t = blockIdx.x, b = blockIdx.y;
    int it = (int)floorf((sqrtf(8.f * (float)t + 1.f) - 1.f) * 0.5f);
    while ((it + 1) * (it + 2) / 2 <= t) ++it;
    while (it * (it + 1) / 2 > t) --it;
    const int jt = t - it * (it + 1) / 2;

    extern __shared__ char smem[];
    const uint32_t sb = smem_u32(smem);
    const int tid = threadIdx.x, lane = tid & 31, w = tid >> 5;

    float acc[4][4][4];
    gemm_1t(g_Qh + ((size_t)b * SS + it * 128) * DD, DD,
            g_Kh + ((size_t)b * SS + jt * 128) * DD, DD,
            16, acc, sb, tid);

    const int tg = lane >> 2, t4 = lane & 3;
    const int wm = w & 1, wn = w >> 1;
    const float scale = 0.03125f;  // 1/sqrt(1024)
    __half* base = g_Ph + (size_t)b * SS * SS;
    float* rs = g_rs + (size_t)b * SS;

#pragma unroll
    for (int i = 0; i < 4; ++i) {
        const int r0 = it * 128 + wm * 64 + i * 16 + tg;
        const int r1 = r0 + 8;
        float sum0 = 0.f, sum1 = 0.f;
#pragma unroll
        for (int j = 0; j < 4; ++j) {
            const int c = jt * 128 + wn * 32 + j * 8 + t4 * 2;
            float e0 = (c     <= r0) ? __expf(acc[i][j][0] * scale) : 0.f;
            float e1 = (c + 1 <= r0) ? __expf(acc[i][j][1] * scale) : 0.f;
            float e2 = (c     <= r1) ? __expf(acc[i][j][2] * scale) : 0.f;
            float e3 = (c + 1 <= r1) ? __expf(acc[i][j][3] * scale) : 0.f;
            *(uint32_t*)(base + (size_t)r0 * SS + c) = packh2(e0, e1);
            *(uint32_t*)(base + (size_t)r1 * SS + c) = packh2(e2, e3);
            sum0 += e0 + e1;
            sum1 += e2 + e3;
        }
        sum0 += __shfl_xor_sync(0xffffffffu, sum0, 1);
        sum0 += __shfl_xor_sync(0xffffffffu, sum0, 2);
        sum1 += __shfl_xor_sync(0xffffffffu, sum1, 1);
        sum1 += __shfl_xor_sync(0xffffffffu, sum1, 2);
        if (t4 == 0) {
            atomicAdd(rs + r0, sum0);
            atomicAdd(rs + r1, sum1);
        }
    }
}

// ---------------------------------------------------------------------------
// 3) PV: O = (Pexp @ V) / rowsum. Heavy row-blocks first. grid (8, 16, 4)
// ---------------------------------------------------------------------------
__global__ void __launch_bounds__(256, 2) pv_gemm(float* __restrict__ out)
{
    extern __shared__ char smem[];
    const uint32_t sb = smem_u32(smem);
    const int tid = threadIdx.x, lane = tid & 31, w = tid >> 5;
    const int n0 = blockIdx.x * 128;
    const int it = 15 - blockIdx.y;   // heavy-first
    const int b = blockIdx.z;

    float acc[4][4][4];
    gemm_1t(g_Ph + ((size_t)b * SS + it * 128) * SS, SS,
            g_Vth + ((size_t)b * DD + n0) * SS, SS,
            (it + 1) * 2, acc, sb, tid);

    const int tg = lane >> 2, t4 = lane & 3;
    const int wm = w & 1, wn = w >> 1;
#pragma unroll
    for (int i = 0; i < 4; ++i) {
        const int rr = it * 128 + wm * 64 + i * 16 + tg;
        const float inv0 = 1.f / g_rs[(size_t)b * SS + rr];
        const float inv1 = 1.f / g_rs[(size_t)b * SS + rr + 8];
        const size_t r = (size_t)b * SS + rr;
#pragma unroll
        for (int j = 0; j < 4; ++j) {
            const int c = n0 + wn * 32 + j * 8 + t4 * 2;
            *(float2*)(out + r * DD + c) =
                make_float2(acc[i][j][0] * inv0, acc[i][j][1] * inv0);
            *(float2*)(out + (r + 8) * DD + c) =
                make_float2(acc[i][j][2] * inv1, acc[i][j][3] * inv1);
        }
    }
}

// ---------------------------------------------------------------------------
// Prep: x -> fp16 hi plane. grid 8192, block 256
// ---------------------------------------------------------------------------
__global__ void __launch_bounds__(256) prep_x_kernel(const float* __restrict__ in)
{
    size_t i = (size_t)blockIdx.x * 256 + threadIdx.x;
    float4 v = ((const float4*)in)[i];
    uint2 H;
    H.x = packh2(v.x, v.y);
    H.y = packh2(v.z, v.w);
    ((uint2*)g_xh)[i] = H;
}

// ---------------------------------------------------------------------------
// Prep: transpose + fp16 W (hi only). grid (32, 32, 3), block (32, 8)
// ---------------------------------------------------------------------------
__global__ void __launch_bounds__(256) prep_w_kernel(
    const float* __restrict__ WQ, const float* __restrict__ WK,
    const float* __restrict__ WV)
{
    __shared__ float t[32][33];
    const float* W = (blockIdx.z == 0) ? WQ : (blockIdx.z == 1) ? WK : WV;
    const int n0 = blockIdx.x * 32, k0 = blockIdx.y * 32;
    const int tx = threadIdx.x, ty = threadIdx.y;
#pragma unroll
    for (int j = 0; j < 32; j += 8)
        t[ty + j][tx] = W[(size_t)(k0 + ty + j) * DD + n0 + tx];
    __syncthreads();
    __half* oh = g_Wth + (size_t)blockIdx.z * DD * DD;
#pragma unroll
    for (int j = 0; j < 32; j += 8) {
        size_t o = (size_t)(n0 + ty + j) * DD + k0 + tx;
        oh[o] = __float2half_rn(t[tx][ty + j]);
    }
}

// ---------------------------------------------------------------------------
extern "C" void kernel_launch(void* const* d_in, const int* in_sizes, int n_in,
                              void* d_out, int out_size)
{
    (void)in_sizes; (void)n_in; (void)out_size;
    const float* x  = (const float*)d_in[0];
    const float* WQ = (const float*)d_in[1];
    const float* WK = (const float*)d_in[2];
    const float* WV = (const float*)d_in[3];
    float* out = (float*)d_out;

    cudaFuncSetAttribute(qkv_gemm,    cudaFuncAttributeMaxDynamicSharedMemorySize, SM_TOT);
    cudaFuncSetAttribute(scores_gemm, cudaFuncAttributeMaxDynamicSharedMemorySize, SM_TOT);
    cudaFuncSetAttribute(pv_gemm,     cudaFuncAttributeMaxDynamicSharedMemorySize, SM_TOT);

    zero_rs<<<8, 1024>>>();
    prep_x_kernel<<<8192, 256>>>(x);
    prep_w_kernel<<<dim3(32, 32, 3), dim3(32, 8)>>>(WQ, WK, WV);
    qkv_gemm<<<dim3(8, 64, 3), 256, SM_TOT>>>();
    scores_gemm<<<dim3(136, 4), 256, SM_TOT>>>();
    pv_gemm<<<dim3(8, 16, 4), 256, SM_TOT>>>(out);
}